// round 1
// baseline (speedup 1.0000x reference)
#include <cuda_runtime.h>
#include <cstdint>

// Problem constants (fixed by the dataset)
#define NN   20000   // nodes
#define IND  256     // in_dim
#define OUTD 128     // out_dim
#define NS   8       // num sectors
#define NK   9       // K = S+1
#define NEP  40000   // edges per sector

// ---------------- scratch (device globals; no allocations allowed) ----------
__device__ float d_zbuf[(size_t)NN * NK * OUTD];      // raw z (pre in_norm): [N,K,OUT]
__device__ float d_H   [(size_t)NS * NN * OUTD];      // per-sector H (out_norm applied)
__device__ float d_zc  [(size_t)NN * NK * OUTD];      // z @ WC * in_norm
__device__ float d_zd  [(size_t)NN * NK * OUTD];      // z @ WD * in_norm

// ---------------- generic SGEMM, N fixed to 128 -----------------------------
// C[M,128] = A[M,Kd] @ B[Kd,128]; optional epilogue row scale rowScale[row/scaleDiv]
__global__ __launch_bounds__(256)
void gemm_n128(const float* __restrict__ A, int lda,
               const float* __restrict__ B, int ldb,
               float* __restrict__ C, int ldc,
               int M, int Kd,
               const float* __restrict__ rowScale, int scaleDiv)
{
    const int BM = 128, BK = 8;
    __shared__ float As[BK][BM];   // A tile, transposed
    __shared__ float Bs[BK][128];

    const int tid = threadIdx.x;               // 256 threads
    const int blockRowBase = blockIdx.x * BM;

    const int tRow = (tid / 16) * 8;            // 0..120
    const int tCol = (tid % 16) * 8;            // 0..120

    const int aRow = tid / 2;                   // 0..127
    const int aCol = (tid % 2) * 4;             // 0 or 4
    const int bRow = tid / 32;                  // 0..7
    const int bCol = (tid % 32) * 4;            // 0..124

    float acc[8][8] = {};

    const int gARow = blockRowBase + aRow;
    const bool aValid = gARow < M;
    const float* Aptr = A + (size_t)gARow * lda;

    for (int k0 = 0; k0 < Kd; k0 += BK) {
        float4 av = make_float4(0.f, 0.f, 0.f, 0.f);
        if (aValid)
            av = *reinterpret_cast<const float4*>(Aptr + k0 + aCol);
        As[aCol + 0][aRow] = av.x;
        As[aCol + 1][aRow] = av.y;
        As[aCol + 2][aRow] = av.z;
        As[aCol + 3][aRow] = av.w;

        float4 bv = *reinterpret_cast<const float4*>(B + (size_t)(k0 + bRow) * ldb + bCol);
        *reinterpret_cast<float4*>(&Bs[bRow][bCol]) = bv;
        __syncthreads();

        #pragma unroll
        for (int k = 0; k < BK; ++k) {
            float ra[8], rb[8];
            #pragma unroll
            for (int i = 0; i < 8; ++i) ra[i] = As[k][tRow + i];
            #pragma unroll
            for (int j = 0; j < 8; ++j) rb[j] = Bs[k][tCol + j];
            #pragma unroll
            for (int i = 0; i < 8; ++i)
                #pragma unroll
                for (int j = 0; j < 8; ++j)
                    acc[i][j] += ra[i] * rb[j];
        }
        __syncthreads();
    }

    #pragma unroll
    for (int i = 0; i < 8; ++i) {
        int gRow = blockRowBase + tRow + i;
        if (gRow >= M) break;
        float s = 1.0f;
        if (scaleDiv) s = rowScale[gRow / scaleDiv];
        float* cp = C + (size_t)gRow * ldc + tCol;
        float4 v0 = make_float4(acc[i][0]*s, acc[i][1]*s, acc[i][2]*s, acc[i][3]*s);
        float4 v1 = make_float4(acc[i][4]*s, acc[i][5]*s, acc[i][6]*s, acc[i][7]*s);
        *reinterpret_cast<float4*>(cp + 0) = v0;
        *reinterpret_cast<float4*>(cp + 4) = v1;
    }
}

// ---------------- edge scatter: z[rows[s,e], 1+s, :] += H[s, cols[s,e], :] --
__global__ __launch_bounds__(256)
void scatter_add(const int* __restrict__ rows, const int* __restrict__ cols,
                 const float* __restrict__ H, float* __restrict__ zbuf)
{
    int gw   = (blockIdx.x * blockDim.x + threadIdx.x) >> 5;   // global warp = edge
    int lane = threadIdx.x & 31;
    if (gw >= NS * NEP) return;
    int s = gw / NEP;
    int e = gw - s * NEP;
    int src = rows[s * NEP + e];   // destination segment (adj row)
    int dst = cols[s * NEP + e];   // gathered node   (adj col)
    const float4* hp = reinterpret_cast<const float4*>(H + ((size_t)s * NN + dst) * OUTD);
    float* zp = zbuf + ((size_t)src * NK + 1 + s) * OUTD;
    float4 v = hp[lane];           // 32 lanes x float4 = 128 floats
    atomicAdd(zp + lane * 4 + 0, v.x);
    atomicAdd(zp + lane * 4 + 1, v.y);
    atomicAdd(zp + lane * 4 + 2, v.z);
    atomicAdd(zp + lane * 4 + 3, v.w);
}

// ---------------- per-node interaction ---------------------------------------
// One block of 128 threads per node. zc/zd already include in_norm.
__global__ __launch_bounds__(128)
void interact(const float* __restrict__ zc, const float* __restrict__ zd,
              const float* __restrict__ gw, const float* __restrict__ gb,
              float* __restrict__ out)
{
    const int n = blockIdx.x;
    const int t = threadIdx.x;           // 0..127 = output dim
    __shared__ float sc[NK][OUTD];
    __shared__ float sd[NK][OUTD];
    __shared__ float ac[NK][NK];         // Gram(zc) -> softmax rows
    __shared__ float ad[NK][NK];         // Gram(zd) -> softmax of (diag - row)
    __shared__ float red[4];
    __shared__ float s_beta;

    const float* zcn = zc + (size_t)n * NK * OUTD;
    const float* zdn = zd + (size_t)n * NK * OUTD;
    #pragma unroll
    for (int r = 0; r < NK; ++r) {
        sc[r][t] = zcn[r * OUTD + t];
        sd[r][t] = zdn[r * OUTD + t];
    }
    __syncthreads();

    // 162 dot products of length 128 (81 for zc-Gram, 81 for zd-Gram)
    const int warp = t >> 5, lane = t & 31;
    for (int d = warp; d < 162; d += 4) {
        int which = (d >= 81);
        int p = which ? d - 81 : d;
        int k = p / 9, j = p - 9 * k;
        const float* a = which ? sd[k] : sc[k];
        const float* b = which ? sd[j] : sc[j];
        float part = 0.f;
        #pragma unroll
        for (int o = 0; o < 4; ++o) part += a[lane + 32 * o] * b[lane + 32 * o];
        #pragma unroll
        for (int off = 16; off; off >>= 1)
            part += __shfl_down_sync(0xffffffffu, part, off);
        if (lane == 0) { if (which) ad[k][j] = part; else ac[k][j] = part; }
    }
    __syncthreads();

    // row softmaxes (9 rows each, tiny)
    if (t < 9) {
        float row[NK]; float m = -1e30f;
        #pragma unroll
        for (int j = 0; j < NK; ++j) { row[j] = ac[t][j]; m = fmaxf(m, row[j]); }
        float ssum = 0.f;
        #pragma unroll
        for (int j = 0; j < NK; ++j) { row[j] = expf(row[j] - m); ssum += row[j]; }
        float inv = 1.f / ssum;
        #pragma unroll
        for (int j = 0; j < NK; ++j) ac[t][j] = row[j] * inv;
    } else if (t >= 16 && t < 25) {
        int k = t - 16;
        float q = ad[k][k];
        float row[NK]; float m = -1e30f;
        #pragma unroll
        for (int j = 0; j < NK; ++j) { row[j] = q - ad[k][j]; m = fmaxf(m, row[j]); }
        float ssum = 0.f;
        #pragma unroll
        for (int j = 0; j < NK; ++j) { row[j] = expf(row[j] - m); ssum += row[j]; }
        float inv = 1.f / ssum;
        #pragma unroll
        for (int j = 0; j < NK; ++j) ad[k][j] = row[j] * inv;
    }
    __syncthreads();

    // z_com = ac @ zc ; z_dis = zd - ad @ zd ; gate
    float zcom[NK], zdis[NK];
    #pragma unroll
    for (int k = 0; k < NK; ++k) {
        float a0 = 0.f, a1 = 0.f;
        #pragma unroll
        for (int j = 0; j < NK; ++j) {
            a0 += ac[k][j] * sc[j][t];
            a1 += ad[k][j] * sd[j][t];
        }
        zcom[k] = a0;
        zdis[k] = sd[k][t] - a1;
    }

    float gp = 0.f;
    #pragma unroll
    for (int k = 0; k < NK; ++k)
        gp += zcom[k] * gw[k * OUTD + t] + zdis[k] * gw[NK * OUTD + k * OUTD + t];
    #pragma unroll
    for (int off = 16; off; off >>= 1)
        gp += __shfl_down_sync(0xffffffffu, gp, off);
    if (lane == 0) red[warp] = gp;
    __syncthreads();
    if (t == 0) {
        float tot = red[0] + red[1] + red[2] + red[3] + gb[0];
        s_beta = 1.f / (1.f + expf(-tot));
    }
    __syncthreads();
    const float beta = s_beta;

    float* op = out + (size_t)n * (NK * OUTD);
    #pragma unroll
    for (int k = 0; k < NK; ++k)
        op[k * OUTD + t] = beta * zcom[k] + (1.f - beta) * zdis[k];
}

// ---------------- launch ------------------------------------------------------
extern "C" void kernel_launch(void* const* d_in, const int* in_sizes, int n_in,
                              void* d_out, int out_size)
{
    const float* x        = (const float*)d_in[0];
    const float* W_self   = (const float*)d_in[1];
    const float* W_sect   = (const float*)d_in[2];
    const float* WC       = (const float*)d_in[3];
    const float* WD       = (const float*)d_in[4];
    const float* gate_w   = (const float*)d_in[5];
    const float* gate_b   = (const float*)d_in[6];
    const float* out_norm = (const float*)d_in[7];
    const float* in_norm  = (const float*)d_in[8];
    const int*   rows     = (const int*)d_in[9];
    const int*   cols     = (const int*)d_in[10];
    float* out = (float*)d_out;

    float *zbuf, *H, *zc, *zd;
    cudaGetSymbolAddress((void**)&zbuf, d_zbuf);
    cudaGetSymbolAddress((void**)&H,    d_H);
    cudaGetSymbolAddress((void**)&zc,   d_zc);
    cudaGetSymbolAddress((void**)&zd,   d_zd);

    // 1) zero z accumulator (k=0 slice gets overwritten by the self GEMM)
    cudaMemsetAsync(zbuf, 0, sizeof(float) * (size_t)NN * NK * OUTD, 0);

    // 2) branch GEMMs: self -> zbuf[:,0,:]; sectors -> H (out_norm in epilogue)
    dim3 g1((NN + 127) / 128);
    gemm_n128<<<g1, 256>>>(x, IND, W_self, OUTD, zbuf, NK * OUTD, NN, IND, nullptr, 0);
    for (int s = 0; s < NS; ++s)
        gemm_n128<<<g1, 256>>>(x, IND, W_sect + (size_t)s * IND * OUTD, OUTD,
                               H + (size_t)s * NN * OUTD, OUTD, NN, IND, out_norm, 1);

    // 3) edge scatter-add into zbuf[:,1+s,:]
    int nWarp = NS * NEP;
    scatter_add<<<(nWarp * 32 + 255) / 256, 256>>>(rows, cols, H, zbuf);

    // 4) zc = (z*in_norm) @ WC, zd = (z*in_norm) @ WD  (in_norm via epilogue)
    dim3 g2(((size_t)NN * NK + 127) / 128);
    gemm_n128<<<g2, 256>>>(zbuf, OUTD, WC, OUTD, zc, OUTD, NN * NK, OUTD, in_norm, NK);
    gemm_n128<<<g2, 256>>>(zbuf, OUTD, WD, OUTD, zd, OUTD, NN * NK, OUTD, in_norm, NK);

    // 5) per-node interaction + gate
    interact<<<NN, 128>>>(zc, zd, gate_w, gate_b, out);
}

// round 4
// speedup vs baseline: 1.8044x; 1.8044x over previous
#include <cuda_runtime.h>
#include <cuda_bf16.h>
#include <cstdint>

// Problem constants (fixed by the dataset)
#define NN   20000   // nodes
#define IND  256     // in_dim
#define OUTD 128     // out_dim
#define NS   8       // num sectors
#define NK   9       // K = S+1
#define NEP  40000   // edges per sector

// ---------------- scratch (device globals; no allocations allowed) ----------
__device__ float d_zbuf[(size_t)NN * NK * OUTD];            // raw z: [N,K,OUT] fp32
__device__ float d_H   [(size_t)NS * NN * OUTD];            // per-sector H (out_norm applied)
__device__ float d_zc  [(size_t)NN * NK * OUTD];            // (z*in_norm) @ WC
__device__ float d_zd  [(size_t)NN * NK * OUTD];            // (z*in_norm) @ WD
// 3-way split-bf16 operands: A' = [hi | lo | hi], B'^T = [hi | hi | lo]
__device__ __nv_bfloat16 d_x2 [(size_t)NN * 3 * IND];         // [N, 768]
__device__ __nv_bfloat16 d_z2 [(size_t)NN * NK * 3 * OUTD];   // [N*K, 384]
__device__ __nv_bfloat16 d_w1t[(size_t)NK * OUTD * 3 * IND];  // [9][128,768]
__device__ __nv_bfloat16 d_w2t[(size_t)2  * OUTD * 3 * OUTD]; // [2][128,384]

// ============================ PTX helpers ====================================
__device__ __forceinline__ uint32_t smem_u32(const void* p) {
    uint32_t a;
    asm("{ .reg .u64 t; cvta.to.shared.u64 t, %1; cvt.u32.u64 %0, t; }" : "=r"(a) : "l"(p));
    return a;
}
__device__ __forceinline__ void ldmx4(uint32_t* r, uint32_t addr) {
    asm volatile("ldmatrix.sync.aligned.m8n8.x4.shared.b16 {%0,%1,%2,%3}, [%4];"
        : "=r"(r[0]), "=r"(r[1]), "=r"(r[2]), "=r"(r[3]) : "r"(addr));
}
__device__ __forceinline__ void mma16816(float* c, const uint32_t* a, uint32_t b0, uint32_t b1) {
    asm volatile("mma.sync.aligned.m16n8k16.row.col.f32.bf16.bf16.f32 "
        "{%0,%1,%2,%3}, {%4,%5,%6,%7}, {%8,%9}, {%0,%1,%2,%3};"
        : "+f"(c[0]), "+f"(c[1]), "+f"(c[2]), "+f"(c[3])
        : "r"(a[0]), "r"(a[1]), "r"(a[2]), "r"(a[3]), "r"(b0), "r"(b1));
}
#define CP_ASYNC16(sp, gp) \
    asm volatile("cp.async.cg.shared.global [%0], [%1], 16;" :: "r"(sp), "l"(gp))
#define CP_COMMIT() asm volatile("cp.async.commit_group;" ::: "memory")
#define CP_WAIT1()  asm volatile("cp.async.wait_group 1;" ::: "memory")
#define CP_WAIT0()  asm volatile("cp.async.wait_group 0;" ::: "memory")

// ============================ conversion kernels =============================
// fp32 [rows, cols] -> A' = [hi | lo | hi] stacked along K (row stride 3*cols)
__global__ __launch_bounds__(256)
void conv_pair(const float* __restrict__ in, __nv_bfloat16* __restrict__ out,
               int rows, int cols)
{
    int i = blockIdx.x * blockDim.x + threadIdx.x;
    if (i >= rows * cols) return;
    int r = i / cols, c = i - r * cols;
    float v = in[i];
    __nv_bfloat16 h = __float2bfloat16(v);
    float lo = v - __bfloat162float(h);
    __nv_bfloat16* op = out + (size_t)r * 3 * cols;
    op[c] = h;
    op[cols + c] = __float2bfloat16(lo);
    op[2 * cols + c] = h;
}

// W[K,128] -> transposed B'^T = [hi | hi | lo] (row stride 3K)
__global__ __launch_bounds__(256)
void conv_w(const float* __restrict__ W0, const float* __restrict__ Ws,
            __nv_bfloat16* __restrict__ out, int K)
{
    int b = blockIdx.y;
    const float* W = (b == 0) ? W0 : Ws + (size_t)(b - 1) * K * OUTD;
    __nv_bfloat16* ob = out + (size_t)b * OUTD * 3 * K;
    int i = blockIdx.x * blockDim.x + threadIdx.x;
    if (i >= K * OUTD) return;
    int k = i / OUTD, n = i - k * OUTD;
    float v = W[i];
    __nv_bfloat16 h = __float2bfloat16(v);
    float lo = v - __bfloat162float(h);
    __nv_bfloat16* row = ob + (size_t)n * 3 * K;
    row[k] = h;
    row[K + k] = h;
    row[2 * K + k] = __float2bfloat16(lo);
}

// ============================ HMMA GEMM =====================================
// C[M,128] = A'[M,Kd](bf16,row-major) @ B'[128,Kd]^T (bf16, n-major rows).
// 128x128 tile per CTA, 256 thr, 8 warps (2m x 4n), warp tile 64x32, BK=32,
// cp.async double buffering, ldmatrix + mma.m16n8k16 bf16->f32.
// mode 0: branch GEMM (branch 0 -> zbuf slice 0; 1..8 -> H with out_norm)
// mode 1: WC/WD GEMM  (branch 0 -> zc; 1 -> zd; scale in_norm[row/9])
#define SSTR 40   // smem row stride in bf16 (conflict-free for ldmatrix)
__global__ __launch_bounds__(256)
void mma_gemm(const __nv_bfloat16* __restrict__ A2, int lda,
              const __nv_bfloat16* __restrict__ Bbase, long bstride,
              int Kd, int M,
              float* __restrict__ zbuf, float* __restrict__ H,
              const float* __restrict__ out_norm, const float* __restrict__ in_norm,
              float* __restrict__ zc, float* __restrict__ zd, int mode)
{
    __shared__ __align__(16) __nv_bfloat16 sA[2][128][SSTR];
    __shared__ __align__(16) __nv_bfloat16 sB[2][128][SSTR];

    const int tid = threadIdx.x;
    const int wid = tid >> 5, lane = tid & 31;
    const int warpM = wid & 1;          // 0..1 -> 64-row half
    const int warpN = wid >> 1;         // 0..3 -> 32-col slice
    const int branch = blockIdx.y;
    const int rowBase = blockIdx.x * 128;

    float* C; int ldc; const float* scale; int sdiv;
    if (mode == 0) {
        if (branch == 0) { C = zbuf; ldc = NK * OUTD; scale = nullptr; sdiv = 0; }
        else { C = H + (size_t)(branch - 1) * NN * OUTD; ldc = OUTD; scale = out_norm; sdiv = 1; }
    } else {
        C = branch ? zd : zc; ldc = OUTD; scale = in_norm; sdiv = NK;
    }
    const __nv_bfloat16* B2 = Bbase + (size_t)branch * bstride;

    const int nC = Kd >> 5;             // chunks of 32 bf16
    float acc[4][4][4] = {};            // [mt][nt][frag]

    // ---- stage loader: 512 x 16B per operand tile, 2 per thread each --------
    auto load_stage = [&](int c, int buf) {
        int k0 = c * 32;
        #pragma unroll
        for (int i = 0; i < 2; ++i) {
            int idx = tid + i * 256;          // 0..511
            int r = idx >> 2, ch = (idx & 3) * 8;
            int grow = rowBase + r; if (grow > M - 1) grow = M - 1;
            const void* gpA = A2 + (size_t)grow * lda + k0 + ch;
            uint32_t spA = smem_u32(&sA[buf][r][ch]);
            CP_ASYNC16(spA, gpA);
            const void* gpB = B2 + (size_t)r * Kd + k0 + ch;
            uint32_t spB = smem_u32(&sB[buf][r][ch]);
            CP_ASYNC16(spB, gpB);
        }
    };

    int buf = 0;
    load_stage(0, 0);
    CP_COMMIT();

    for (int c = 0; c < nC; ++c) {
        if (c + 1 < nC) {
            load_stage(c + 1, buf ^ 1);
            CP_COMMIT();
            CP_WAIT1();
        } else {
            CP_WAIT0();
        }
        __syncthreads();

        #pragma unroll
        for (int ks = 0; ks < 2; ++ks) {          // two k16 steps per BK=32
            uint32_t a[4][4];
            #pragma unroll
            for (int mt = 0; mt < 4; ++mt) {
                uint32_t ad = smem_u32(&sA[buf][warpM * 64 + mt * 16 + (lane & 15)]
                                          [ks * 16 + (lane >> 4) * 8]);
                ldmx4(a[mt], ad);
            }
            uint32_t b[2][4];
            #pragma unroll
            for (int nt2 = 0; nt2 < 2; ++nt2) {
                uint32_t bd = smem_u32(&sB[buf][warpN * 32 + nt2 * 16 + (lane & 15)]
                                          [ks * 16 + (lane >> 4) * 8]);
                ldmx4(b[nt2], bd);
            }
            #pragma unroll
            for (int mt = 0; mt < 4; ++mt)
                #pragma unroll
                for (int nt2 = 0; nt2 < 2; ++nt2) {
                    mma16816(acc[mt][nt2 * 2 + 0], a[mt], b[nt2][0], b[nt2][2]);
                    mma16816(acc[mt][nt2 * 2 + 1], a[mt], b[nt2][1], b[nt2][3]);
                }
        }
        __syncthreads();
        buf ^= 1;
    }

    // ---- epilogue: c frag (g=lane>>2, t=lane&3): rows g,g+8; cols 2t,2t+1 ----
    const int g = lane >> 2, t4 = lane & 3;
    #pragma unroll
    for (int mt = 0; mt < 4; ++mt) {
        int row0 = rowBase + warpM * 64 + mt * 16 + g;
        int row1 = row0 + 8;
        float s0 = 1.f, s1 = 1.f;
        if (scale) {
            if (row0 < M) s0 = scale[(sdiv == 1) ? row0 : row0 / NK];
            if (row1 < M) s1 = scale[(sdiv == 1) ? row1 : row1 / NK];
        }
        #pragma unroll
        for (int nt = 0; nt < 4; ++nt) {
            int col = warpN * 32 + nt * 8 + 2 * t4;
            if (row0 < M) {
                float2 v = make_float2(acc[mt][nt][0] * s0, acc[mt][nt][1] * s0);
                *reinterpret_cast<float2*>(C + (size_t)row0 * ldc + col) = v;
            }
            if (row1 < M) {
                float2 v = make_float2(acc[mt][nt][2] * s1, acc[mt][nt][3] * s1);
                *reinterpret_cast<float2*>(C + (size_t)row1 * ldc + col) = v;
            }
        }
    }
}

// ---------------- edge scatter: z[rows[s,e], 1+s, :] += H[s, cols[s,e], :] --
__global__ __launch_bounds__(256)
void scatter_add(const int* __restrict__ rows, const int* __restrict__ cols,
                 const float* __restrict__ H, float* __restrict__ zbuf)
{
    int gw   = (blockIdx.x * blockDim.x + threadIdx.x) >> 5;   // global warp = edge
    int lane = threadIdx.x & 31;
    if (gw >= NS * NEP) return;
    int s = gw / NEP;
    int e = gw - s * NEP;
    int src = rows[s * NEP + e];
    int dst = cols[s * NEP + e];
    const float4* hp = reinterpret_cast<const float4*>(H + ((size_t)s * NN + dst) * OUTD);
    float* zp = zbuf + ((size_t)src * NK + 1 + s) * OUTD + lane * 4;
    float4 v = hp[lane];
    asm volatile("red.global.add.v4.f32 [%0], {%1, %2, %3, %4};"
                 :: "l"(zp), "f"(v.x), "f"(v.y), "f"(v.z), "f"(v.w) : "memory");
}

// ---------------- per-node interaction (verified round 1) -------------------
__global__ __launch_bounds__(128)
void interact(const float* __restrict__ zc, const float* __restrict__ zd,
              const float* __restrict__ gw, const float* __restrict__ gb,
              float* __restrict__ out)
{
    const int n = blockIdx.x;
    const int t = threadIdx.x;
    __shared__ float sc[NK][OUTD];
    __shared__ float sd[NK][OUTD];
    __shared__ float ac[NK][NK];
    __shared__ float ad[NK][NK];
    __shared__ float red[4];
    __shared__ float s_beta;

    const float* zcn = zc + (size_t)n * NK * OUTD;
    const float* zdn = zd + (size_t)n * NK * OUTD;
    #pragma unroll
    for (int r = 0; r < NK; ++r) {
        sc[r][t] = zcn[r * OUTD + t];
        sd[r][t] = zdn[r * OUTD + t];
    }
    __syncthreads();

    const int warp = t >> 5, lane = t & 31;
    for (int d = warp; d < 162; d += 4) {
        int which = (d >= 81);
        int p = which ? d - 81 : d;
        int k = p / 9, j = p - 9 * k;
        const float* a = which ? sd[k] : sc[k];
        const float* b = which ? sd[j] : sc[j];
        float part = 0.f;
        #pragma unroll
        for (int o = 0; o < 4; ++o) part += a[lane + 32 * o] * b[lane + 32 * o];
        #pragma unroll
        for (int off = 16; off; off >>= 1)
            part += __shfl_down_sync(0xffffffffu, part, off);
        if (lane == 0) { if (which) ad[k][j] = part; else ac[k][j] = part; }
    }
    __syncthreads();

    if (t < 9) {
        float row[NK]; float m = -1e30f;
        #pragma unroll
        for (int j = 0; j < NK; ++j) { row[j] = ac[t][j]; m = fmaxf(m, row[j]); }
        float ssum = 0.f;
        #pragma unroll
        for (int j = 0; j < NK; ++j) { row[j] = expf(row[j] - m); ssum += row[j]; }
        float inv = 1.f / ssum;
        #pragma unroll
        for (int j = 0; j < NK; ++j) ac[t][j] = row[j] * inv;
    } else if (t >= 16 && t < 25) {
        int k = t - 16;
        float q = ad[k][k];
        float row[NK]; float m = -1e30f;
        #pragma unroll
        for (int j = 0; j < NK; ++j) { row[j] = q - ad[k][j]; m = fmaxf(m, row[j]); }
        float ssum = 0.f;
        #pragma unroll
        for (int j = 0; j < NK; ++j) { row[j] = expf(row[j] - m); ssum += row[j]; }
        float inv = 1.f / ssum;
        #pragma unroll
        for (int j = 0; j < NK; ++j) ad[k][j] = row[j] * inv;
    }
    __syncthreads();

    float zcom[NK], zdis[NK];
    #pragma unroll
    for (int k = 0; k < NK; ++k) {
        float a0 = 0.f, a1 = 0.f;
        #pragma unroll
        for (int j = 0; j < NK; ++j) {
            a0 += ac[k][j] * sc[j][t];
            a1 += ad[k][j] * sd[j][t];
        }
        zcom[k] = a0;
        zdis[k] = sd[k][t] - a1;
    }

    float gp = 0.f;
    #pragma unroll
    for (int k = 0; k < NK; ++k)
        gp += zcom[k] * gw[k * OUTD + t] + zdis[k] * gw[NK * OUTD + k * OUTD + t];
    #pragma unroll
    for (int off = 16; off; off >>= 1)
        gp += __shfl_down_sync(0xffffffffu, gp, off);
    if (lane == 0) red[warp] = gp;
    __syncthreads();
    if (t == 0) {
        float tot = red[0] + red[1] + red[2] + red[3] + gb[0];
        s_beta = 1.f / (1.f + expf(-tot));
    }
    __syncthreads();
    const float beta = s_beta;

    float* op = out + (size_t)n * (NK * OUTD);
    #pragma unroll
    for (int k = 0; k < NK; ++k)
        op[k * OUTD + t] = beta * zcom[k] + (1.f - beta) * zdis[k];
}

// ---------------- launch ------------------------------------------------------
extern "C" void kernel_launch(void* const* d_in, const int* in_sizes, int n_in,
                              void* d_out, int out_size)
{
    const float* x        = (const float*)d_in[0];
    const float* W_self   = (const float*)d_in[1];
    const float* W_sect   = (const float*)d_in[2];
    const float* WC       = (const float*)d_in[3];
    const float* WD       = (const float*)d_in[4];
    const float* gate_w   = (const float*)d_in[5];
    const float* gate_b   = (const float*)d_in[6];
    const float* out_norm = (const float*)d_in[7];
    const float* in_norm  = (const float*)d_in[8];
    const int*   rows     = (const int*)d_in[9];
    const int*   cols     = (const int*)d_in[10];
    float* out = (float*)d_out;

    float *zbuf, *H, *zc, *zd;
    __nv_bfloat16 *x2, *z2, *w1t, *w2t;
    cudaGetSymbolAddress((void**)&zbuf, d_zbuf);
    cudaGetSymbolAddress((void**)&H,    d_H);
    cudaGetSymbolAddress((void**)&zc,   d_zc);
    cudaGetSymbolAddress((void**)&zd,   d_zd);
    cudaGetSymbolAddress((void**)&x2,   d_x2);
    cudaGetSymbolAddress((void**)&z2,   d_z2);
    cudaGetSymbolAddress((void**)&w1t,  d_w1t);
    cudaGetSymbolAddress((void**)&w2t,  d_w2t);

    // 1) zero z accumulator
    cudaMemsetAsync(zbuf, 0, sizeof(float) * (size_t)NN * NK * OUTD, 0);

    // 2) 3-way split-bf16 conversions (x, weights)
    conv_pair<<<(NN * IND + 255) / 256, 256>>>(x, x2, NN, IND);
    conv_w<<<dim3((IND * OUTD + 255) / 256, NK), 256>>>(W_self, W_sect, w1t, IND);
    conv_w<<<dim3((OUTD * OUTD + 255) / 256, 2), 256>>>(WC, WD, w2t, OUTD);

    // 3) batched branch GEMMs on tensor cores (9 branches, Kd = 768 bf16)
    mma_gemm<<<dim3((NN + 127) / 128, NK), 256>>>(
        x2, 3 * IND, w1t, (long)OUTD * 3 * IND, 3 * IND, NN,
        zbuf, H, out_norm, in_norm, zc, zd, 0);

    // 4) edge scatter-add into zbuf[:,1+s,:]
    int nWarp = NS * NEP;
    scatter_add<<<(nWarp * 32 + 255) / 256, 256>>>(rows, cols, H, zbuf);

    // 5) convert z -> bf16 triple, then batched WC/WD GEMMs (Kd = 384 bf16)
    conv_pair<<<(NN * NK * OUTD + 255) / 256, 256>>>(zbuf, z2, NN * NK, OUTD);
    mma_gemm<<<dim3((NN * NK + 127) / 128, 2), 256>>>(
        z2, 3 * OUTD, w2t, (long)OUTD * 3 * OUTD, 3 * OUTD, NN * NK,
        zbuf, H, out_norm, in_norm, zc, zd, 1);

    // 6) per-node interaction + gate
    interact<<<NN, 128>>>(zc, zd, gate_w, gate_b, out);
}

// round 5
// speedup vs baseline: 1.9405x; 1.0754x over previous
#include <cuda_runtime.h>
#include <cuda_bf16.h>
#include <cstdint>

// Problem constants (fixed by the dataset)
#define NN   20000   // nodes
#define IND  256     // in_dim
#define OUTD 128     // out_dim
#define NS   8       // num sectors
#define NK   9       // K = S+1
#define NEP  40000   // edges per sector

// ---------------- scratch (device globals; no allocations allowed) ----------
__device__ float d_zbuf[(size_t)NN * NK * OUTD];            // raw z: [N,K,OUT] fp32
__device__ float d_H   [(size_t)NS * NN * OUTD];            // per-sector H (out_norm applied)
__device__ float d_zc  [(size_t)NN * NK * OUTD];            // (z*in_norm) @ WC
__device__ float d_zd  [(size_t)NN * NK * OUTD];            // (z*in_norm) @ WD
// split-bf16 operands stored compactly as [hi | lo]; the GEMM remaps the
// logical 3-block sequence A:[h|l|h], B:[h|h|l] onto these.
__device__ __nv_bfloat16 d_x2 [(size_t)NN * 2 * IND];         // [N, 512]
__device__ __nv_bfloat16 d_z2 [(size_t)NN * NK * 2 * OUTD];   // [N*K, 256]
__device__ __nv_bfloat16 d_w1t[(size_t)NK * OUTD * 2 * IND];  // [9][128,512]
__device__ __nv_bfloat16 d_w2t[(size_t)2  * OUTD * 2 * OUTD]; // [2][128,256]

// ============================ PTX helpers ====================================
__device__ __forceinline__ uint32_t smem_u32(const void* p) {
    uint32_t a;
    asm("{ .reg .u64 t; cvta.to.shared.u64 t, %1; cvt.u32.u64 %0, t; }" : "=r"(a) : "l"(p));
    return a;
}
__device__ __forceinline__ void ldmx4(uint32_t* r, uint32_t addr) {
    asm volatile("ldmatrix.sync.aligned.m8n8.x4.shared.b16 {%0,%1,%2,%3}, [%4];"
        : "=r"(r[0]), "=r"(r[1]), "=r"(r[2]), "=r"(r[3]) : "r"(addr));
}
__device__ __forceinline__ void mma16816(float* c, const uint32_t* a, uint32_t b0, uint32_t b1) {
    asm volatile("mma.sync.aligned.m16n8k16.row.col.f32.bf16.bf16.f32 "
        "{%0,%1,%2,%3}, {%4,%5,%6,%7}, {%8,%9}, {%0,%1,%2,%3};"
        : "+f"(c[0]), "+f"(c[1]), "+f"(c[2]), "+f"(c[3])
        : "r"(a[0]), "r"(a[1]), "r"(a[2]), "r"(a[3]), "r"(b0), "r"(b1));
}
#define CP_ASYNC16(sp, gp) \
    asm volatile("cp.async.cg.shared.global [%0], [%1], 16;" :: "r"(sp), "l"(gp))
#define CP_COMMIT() asm volatile("cp.async.commit_group;" ::: "memory")
#define CP_WAIT1()  asm volatile("cp.async.wait_group 1;" ::: "memory")
#define CP_WAIT0()  asm volatile("cp.async.wait_group 0;" ::: "memory")

// ============================ conversion kernels =============================
// fp32 [rows, cols] -> [hi | lo] stacked along K (row stride 2*cols)
__global__ __launch_bounds__(256)
void conv_pair(const float* __restrict__ in, __nv_bfloat16* __restrict__ out,
               int rows, int cols)
{
    int i = blockIdx.x * blockDim.x + threadIdx.x;
    if (i >= rows * cols) return;
    int r = i / cols, c = i - r * cols;
    float v = in[i];
    __nv_bfloat16 h = __float2bfloat16(v);
    float lo = v - __bfloat162float(h);
    __nv_bfloat16* op = out + (size_t)r * 2 * cols;
    op[c] = h;
    op[cols + c] = __float2bfloat16(lo);
}

// W[K,128] -> transposed [hi | lo] (row stride 2K)
__global__ __launch_bounds__(256)
void conv_w(const float* __restrict__ W0, const float* __restrict__ Ws,
            __nv_bfloat16* __restrict__ out, int K)
{
    int b = blockIdx.y;
    const float* W = (b == 0) ? W0 : Ws + (size_t)(b - 1) * K * OUTD;
    __nv_bfloat16* ob = out + (size_t)b * OUTD * 2 * K;
    int i = blockIdx.x * blockDim.x + threadIdx.x;
    if (i >= K * OUTD) return;
    int k = i / OUTD, n = i - k * OUTD;
    float v = W[i];
    __nv_bfloat16 h = __float2bfloat16(v);
    float lo = v - __bfloat162float(h);
    __nv_bfloat16* row = ob + (size_t)n * 2 * K;
    row[k] = h;
    row[K + k] = __float2bfloat16(lo);
}

// ============================ HMMA GEMM =====================================
// Logical C[M,128] = A'[M,3*Ka] @ B'[128,3*Ka]^T with the split-3 block
// sequence A:[h|l|h], B:[h|h|l], stored physically as [h|l] (width 2*Ka).
// 128x128 tile/CTA, 256 thr, 8 warps (2m x 4n), BK=64, 3-stage cp.async ring.
// mode 0: branch GEMM (branch 0 -> zbuf slice 0; 1..8 -> H with out_norm)
// mode 1: WC/WD GEMM  (branch 0 -> zc; 1 -> zd; scale in_norm[row/9])
#define SROW 144                      // smem row pitch bytes (64 bf16 + 8 pad)
#define ATILE (128 * SROW)            // 18432 B
#define STAGE_SZ (2 * ATILE)          // A + B per stage
#define NSTAGE 3
#define SMEM_TOT (NSTAGE * STAGE_SZ)  // 110592 B

__global__ __launch_bounds__(256, 2)
void mma_gemm(const __nv_bfloat16* __restrict__ A2,
              const __nv_bfloat16* __restrict__ Bbase,
              int Ka, int M,
              float* __restrict__ zbuf, float* __restrict__ H,
              const float* __restrict__ out_norm, const float* __restrict__ in_norm,
              float* __restrict__ zc, float* __restrict__ zd, int mode)
{
    extern __shared__ __align__(16) char smem[];

    const int tid = threadIdx.x;
    const int wid = tid >> 5, lane = tid & 31;
    const int warpM = wid & 1;          // 0..1 -> 64-row half
    const int warpN = wid >> 1;         // 0..3 -> 32-col slice
    const int branch = blockIdx.y;
    const int rowBase = blockIdx.x * 128;
    const int lda = 2 * Ka;             // physical row width (bf16)
    const int q  = Ka >> 6;             // 64-col chunks per block
    const int nC = 3 * q;               // logical chunks

    float* C; int ldc; const float* scale; int sdiv;
    if (mode == 0) {
        if (branch == 0) { C = zbuf; ldc = NK * OUTD; scale = nullptr; sdiv = 0; }
        else { C = H + (size_t)(branch - 1) * NN * OUTD; ldc = OUTD; scale = out_norm; sdiv = 1; }
    } else {
        C = branch ? zd : zc; ldc = OUTD; scale = in_norm; sdiv = NK;
    }
    const __nv_bfloat16* B2 = Bbase + (size_t)branch * OUTD * lda;

    const uint32_t smemBase = smem_u32(smem);
    float acc[4][4][4] = {};            // [mt][nt][frag]

    // ---- stage loader: A,B tiles 128 x 64 bf16; 1024 16B segs each ----------
    auto load_stage = [&](int c, int buf) {
        int blk = c / q, off = c - blk * q;
        int k0A = ((blk & 1)  * q + off) * 64;   // A blocks: h, l, h
        int k0B = ((blk >> 1) * q + off) * 64;   // B blocks: h, h, l
        char* sAb = smem + buf * STAGE_SZ;
        char* sBb = sAb + ATILE;
        #pragma unroll
        for (int i = 0; i < 4; ++i) {
            int idx = tid + i * 256;             // 0..1023
            int r = idx >> 3, c16 = idx & 7;
            int grow = rowBase + r; if (grow > M - 1) grow = M - 1;
            CP_ASYNC16(smem_u32(sAb + r * SROW + c16 * 16),
                       A2 + (size_t)grow * lda + k0A + c16 * 8);
            CP_ASYNC16(smem_u32(sBb + r * SROW + c16 * 16),
                       B2 + (size_t)r * lda + k0B + c16 * 8);
        }
    };

    load_stage(0, 0); CP_COMMIT();
    load_stage(1, 1); CP_COMMIT();

    for (int c = 0; c < nC; ++c) {
        if (c + 1 < nC) CP_WAIT1(); else CP_WAIT0();
        __syncthreads();                          // stage c ready; c-1 consumed
        if (c + 2 < nC) { load_stage(c + 2, (c + 2) % NSTAGE); CP_COMMIT(); }

        const uint32_t sAb = smemBase + (c % NSTAGE) * STAGE_SZ;
        const uint32_t sBb = sAb + ATILE;
        #pragma unroll
        for (int ks = 0; ks < 4; ++ks) {          // four k16 steps per BK=64
            const uint32_t colOff = (ks * 16 + (lane >> 4) * 8) * 2;
            uint32_t a[4][4];
            #pragma unroll
            for (int mt = 0; mt < 4; ++mt)
                ldmx4(a[mt], sAb + (warpM * 64 + mt * 16 + (lane & 15)) * SROW + colOff);
            uint32_t b[2][4];
            #pragma unroll
            for (int nt2 = 0; nt2 < 2; ++nt2)
                ldmx4(b[nt2], sBb + (warpN * 32 + nt2 * 16 + (lane & 15)) * SROW + colOff);
            #pragma unroll
            for (int mt = 0; mt < 4; ++mt)
                #pragma unroll
                for (int nt2 = 0; nt2 < 2; ++nt2) {
                    mma16816(acc[mt][nt2 * 2 + 0], a[mt], b[nt2][0], b[nt2][2]);
                    mma16816(acc[mt][nt2 * 2 + 1], a[mt], b[nt2][1], b[nt2][3]);
                }
        }
    }

    // ---- epilogue: c frag (g=lane>>2, t=lane&3): rows g,g+8; cols 2t,2t+1 ----
    const int g = lane >> 2, t4 = lane & 3;
    #pragma unroll
    for (int mt = 0; mt < 4; ++mt) {
        int row0 = rowBase + warpM * 64 + mt * 16 + g;
        int row1 = row0 + 8;
        float s0 = 1.f, s1 = 1.f;
        if (scale) {
            if (row0 < M) s0 = scale[(sdiv == 1) ? row0 : row0 / NK];
            if (row1 < M) s1 = scale[(sdiv == 1) ? row1 : row1 / NK];
        }
        #pragma unroll
        for (int nt = 0; nt < 4; ++nt) {
            int col = warpN * 32 + nt * 8 + 2 * t4;
            if (row0 < M) {
                float2 v = make_float2(acc[mt][nt][0] * s0, acc[mt][nt][1] * s0);
                *reinterpret_cast<float2*>(C + (size_t)row0 * ldc + col) = v;
            }
            if (row1 < M) {
                float2 v = make_float2(acc[mt][nt][2] * s1, acc[mt][nt][3] * s1);
                *reinterpret_cast<float2*>(C + (size_t)row1 * ldc + col) = v;
            }
        }
    }
}

// ---------------- edge scatter: z[rows[s,e], 1+s, :] += H[s, cols[s,e], :] --
__global__ __launch_bounds__(256)
void scatter_add(const int* __restrict__ rows, const int* __restrict__ cols,
                 const float* __restrict__ H, float* __restrict__ zbuf)
{
    int gw   = (blockIdx.x * blockDim.x + threadIdx.x) >> 5;   // global warp = edge
    int lane = threadIdx.x & 31;
    if (gw >= NS * NEP) return;
    int s = gw / NEP;
    int e = gw - s * NEP;
    int src = rows[s * NEP + e];
    int dst = cols[s * NEP + e];
    const float4* hp = reinterpret_cast<const float4*>(H + ((size_t)s * NN + dst) * OUTD);
    float* zp = zbuf + ((size_t)src * NK + 1 + s) * OUTD + lane * 4;
    float4 v = hp[lane];
    asm volatile("red.global.add.v4.f32 [%0], {%1, %2, %3, %4};"
                 :: "l"(zp), "f"(v.x), "f"(v.y), "f"(v.z), "f"(v.w) : "memory");
}

// ---------------- per-node interaction (verified) ----------------------------
__global__ __launch_bounds__(128)
void interact(const float* __restrict__ zc, const float* __restrict__ zd,
              const float* __restrict__ gw, const float* __restrict__ gb,
              float* __restrict__ out)
{
    const int n = blockIdx.x;
    const int t = threadIdx.x;
    __shared__ float sc[NK][OUTD];
    __shared__ float sd[NK][OUTD];
    __shared__ float ac[NK][NK];
    __shared__ float ad[NK][NK];
    __shared__ float red[4];
    __shared__ float s_beta;

    const float* zcn = zc + (size_t)n * NK * OUTD;
    const float* zdn = zd + (size_t)n * NK * OUTD;
    #pragma unroll
    for (int r = 0; r < NK; ++r) {
        sc[r][t] = zcn[r * OUTD + t];
        sd[r][t] = zdn[r * OUTD + t];
    }
    __syncthreads();

    const int warp = t >> 5, lane = t & 31;
    for (int d = warp; d < 162; d += 4) {
        int which = (d >= 81);
        int p = which ? d - 81 : d;
        int k = p / 9, j = p - 9 * k;
        const float* a = which ? sd[k] : sc[k];
        const float* b = which ? sd[j] : sc[j];
        float part = 0.f;
        #pragma unroll
        for (int o = 0; o < 4; ++o) part += a[lane + 32 * o] * b[lane + 32 * o];
        #pragma unroll
        for (int off = 16; off; off >>= 1)
            part += __shfl_down_sync(0xffffffffu, part, off);
        if (lane == 0) { if (which) ad[k][j] = part; else ac[k][j] = part; }
    }
    __syncthreads();

    if (t < 9) {
        float row[NK]; float m = -1e30f;
        #pragma unroll
        for (int j = 0; j < NK; ++j) { row[j] = ac[t][j]; m = fmaxf(m, row[j]); }
        float ssum = 0.f;
        #pragma unroll
        for (int j = 0; j < NK; ++j) { row[j] = expf(row[j] - m); ssum += row[j]; }
        float inv = 1.f / ssum;
        #pragma unroll
        for (int j = 0; j < NK; ++j) ac[t][j] = row[j] * inv;
    } else if (t >= 16 && t < 25) {
        int k = t - 16;
        float q = ad[k][k];
        float row[NK]; float m = -1e30f;
        #pragma unroll
        for (int j = 0; j < NK; ++j) { row[j] = q - ad[k][j]; m = fmaxf(m, row[j]); }
        float ssum = 0.f;
        #pragma unroll
        for (int j = 0; j < NK; ++j) { row[j] = expf(row[j] - m); ssum += row[j]; }
        float inv = 1.f / ssum;
        #pragma unroll
        for (int j = 0; j < NK; ++j) ad[k][j] = row[j] * inv;
    }
    __syncthreads();

    float zcom[NK], zdis[NK];
    #pragma unroll
    for (int k = 0; k < NK; ++k) {
        float a0 = 0.f, a1 = 0.f;
        #pragma unroll
        for (int j = 0; j < NK; ++j) {
            a0 += ac[k][j] * sc[j][t];
            a1 += ad[k][j] * sd[j][t];
        }
        zcom[k] = a0;
        zdis[k] = sd[k][t] - a1;
    }

    float gp = 0.f;
    #pragma unroll
    for (int k = 0; k < NK; ++k)
        gp += zcom[k] * gw[k * OUTD + t] + zdis[k] * gw[NK * OUTD + k * OUTD + t];
    #pragma unroll
    for (int off = 16; off; off >>= 1)
        gp += __shfl_down_sync(0xffffffffu, gp, off);
    if (lane == 0) red[warp] = gp;
    __syncthreads();
    if (t == 0) {
        float tot = red[0] + red[1] + red[2] + red[3] + gb[0];
        s_beta = 1.f / (1.f + expf(-tot));
    }
    __syncthreads();
    const float beta = s_beta;

    float* op = out + (size_t)n * (NK * OUTD);
    #pragma unroll
    for (int k = 0; k < NK; ++k)
        op[k * OUTD + t] = beta * zcom[k] + (1.f - beta) * zdis[k];
}

// ---------------- launch ------------------------------------------------------
extern "C" void kernel_launch(void* const* d_in, const int* in_sizes, int n_in,
                              void* d_out, int out_size)
{
    const float* x        = (const float*)d_in[0];
    const float* W_self   = (const float*)d_in[1];
    const float* W_sect   = (const float*)d_in[2];
    const float* WC       = (const float*)d_in[3];
    const float* WD       = (const float*)d_in[4];
    const float* gate_w   = (const float*)d_in[5];
    const float* gate_b   = (const float*)d_in[6];
    const float* out_norm = (const float*)d_in[7];
    const float* in_norm  = (const float*)d_in[8];
    const int*   rows     = (const int*)d_in[9];
    const int*   cols     = (const int*)d_in[10];
    float* out = (float*)d_out;

    float *zbuf, *H, *zc, *zd;
    __nv_bfloat16 *x2, *z2, *w1t, *w2t;
    cudaGetSymbolAddress((void**)&zbuf, d_zbuf);
    cudaGetSymbolAddress((void**)&H,    d_H);
    cudaGetSymbolAddress((void**)&zc,   d_zc);
    cudaGetSymbolAddress((void**)&zd,   d_zd);
    cudaGetSymbolAddress((void**)&x2,   d_x2);
    cudaGetSymbolAddress((void**)&z2,   d_z2);
    cudaGetSymbolAddress((void**)&w1t,  d_w1t);
    cudaGetSymbolAddress((void**)&w2t,  d_w2t);

    // allow >48KB dynamic smem for the GEMM (idempotent; host-side only)
    cudaFuncSetAttribute(mma_gemm, cudaFuncAttributeMaxDynamicSharedMemorySize, SMEM_TOT);

    // 1) zero z accumulator
    cudaMemsetAsync(zbuf, 0, sizeof(float) * (size_t)NN * NK * OUTD, 0);

    // 2) split-bf16 [hi|lo] conversions (x, weights)
    conv_pair<<<(NN * IND + 255) / 256, 256>>>(x, x2, NN, IND);
    conv_w<<<dim3((IND * OUTD + 255) / 256, NK), 256>>>(W_self, W_sect, w1t, IND);
    conv_w<<<dim3((OUTD * OUTD + 255) / 256, 2), 256>>>(WC, WD, w2t, OUTD);

    // 3) batched branch GEMMs on tensor cores (9 branches, Ka = 256)
    mma_gemm<<<dim3((NN + 127) / 128, NK), 256, SMEM_TOT>>>(
        x2, w1t, IND, NN, zbuf, H, out_norm, in_norm, zc, zd, 0);

    // 4) edge scatter-add into zbuf[:,1+s,:]
    int nWarp = NS * NEP;
    scatter_add<<<(nWarp * 32 + 255) / 256, 256>>>(rows, cols, H, zbuf);

    // 5) convert z -> [hi|lo], then batched WC/WD GEMMs (Ka = 128)
    conv_pair<<<(NN * NK * OUTD + 255) / 256, 256>>>(zbuf, z2, NN * NK, OUTD);
    mma_gemm<<<dim3((NN * NK + 127) / 128, 2), 256, SMEM_TOT>>>(
        z2, w2t, OUTD, NN * NK, zbuf, H, out_norm, in_norm, zc, zd, 1);

    // 6) per-node interaction + gate
    interact<<<NN, 128>>>(zc, zd, gate_w, gate_b, out);
}

// round 6
// speedup vs baseline: 2.1814x; 1.1242x over previous
#include <cuda_runtime.h>
#include <cuda_bf16.h>
#include <cstdint>

// Problem constants (fixed by the dataset)
#define NN   20000   // nodes
#define IND  256     // in_dim
#define OUTD 128     // out_dim
#define NS   8       // num sectors
#define NK   9       // K = S+1
#define NEP  40000   // edges per sector
#define EMAX 64      // per-(sector,src) edge-list capacity (Poisson(2) degrees)

// ---------------- scratch (device globals; no allocations allowed) ----------
__device__ float d_H   [(size_t)NS * NN * OUTD];            // per-sector H (out_norm applied)
__device__ float d_zc  [(size_t)NN * NK * OUTD];            // (z*in_norm) @ WC
__device__ float d_zd  [(size_t)NN * NK * OUTD];            // (z*in_norm) @ WD
// split-bf16 operands stored compactly as [hi | lo]; the GEMM remaps the
// logical 3-block sequence A:[h|l|h], B:[h|h|l] onto these.
__device__ __nv_bfloat16 d_x2 [(size_t)NN * 2 * IND];         // [N, 512]
__device__ __nv_bfloat16 d_z2 [(size_t)NN * NK * 2 * OUTD];   // [N*K, 256]
__device__ __nv_bfloat16 d_w1t[(size_t)NK * OUTD * 2 * IND];  // [9][128,512]
__device__ __nv_bfloat16 d_w2t[(size_t)2  * OUTD * 2 * OUTD]; // [2][128,256]
// CSR-ish fixed-capacity edge lists, rebuilt every call
__device__ int d_cnt [(size_t)NS * NN];
__device__ int d_eidx[(size_t)NS * NN * EMAX];

// ============================ PTX helpers ====================================
__device__ __forceinline__ uint32_t smem_u32(const void* p) {
    uint32_t a;
    asm("{ .reg .u64 t; cvta.to.shared.u64 t, %1; cvt.u32.u64 %0, t; }" : "=r"(a) : "l"(p));
    return a;
}
__device__ __forceinline__ void ldmx4(uint32_t* r, uint32_t addr) {
    asm volatile("ldmatrix.sync.aligned.m8n8.x4.shared.b16 {%0,%1,%2,%3}, [%4];"
        : "=r"(r[0]), "=r"(r[1]), "=r"(r[2]), "=r"(r[3]) : "r"(addr));
}
__device__ __forceinline__ void mma16816(float* c, const uint32_t* a, uint32_t b0, uint32_t b1) {
    asm volatile("mma.sync.aligned.m16n8k16.row.col.f32.bf16.bf16.f32 "
        "{%0,%1,%2,%3}, {%4,%5,%6,%7}, {%8,%9}, {%0,%1,%2,%3};"
        : "+f"(c[0]), "+f"(c[1]), "+f"(c[2]), "+f"(c[3])
        : "r"(a[0]), "r"(a[1]), "r"(a[2]), "r"(a[3]), "r"(b0), "r"(b1));
}
#define CP_ASYNC16(sp, gp) \
    asm volatile("cp.async.cg.shared.global [%0], [%1], 16;" :: "r"(sp), "l"(gp))
#define CP_COMMIT() asm volatile("cp.async.commit_group;" ::: "memory")
#define CP_WAIT1()  asm volatile("cp.async.wait_group 1;" ::: "memory")
#define CP_WAIT0()  asm volatile("cp.async.wait_group 0;" ::: "memory")

// ============================ conversion kernels =============================
// fp32 [rows, cols] -> [hi | lo] stacked along K (row stride 2*cols)
__global__ __launch_bounds__(256)
void conv_pair(const float* __restrict__ in, __nv_bfloat16* __restrict__ out,
               int rows, int cols)
{
    int i = blockIdx.x * blockDim.x + threadIdx.x;
    if (i >= rows * cols) return;
    int r = i / cols, c = i - r * cols;
    float v = in[i];
    __nv_bfloat16 h = __float2bfloat16(v);
    float lo = v - __bfloat162float(h);
    __nv_bfloat16* op = out + (size_t)r * 2 * cols;
    op[c] = h;
    op[cols + c] = __float2bfloat16(lo);
}

// W[K,128] -> transposed [hi | lo] (row stride 2K)
__global__ __launch_bounds__(256)
void conv_w(const float* __restrict__ W0, const float* __restrict__ Ws,
            __nv_bfloat16* __restrict__ out, int K)
{
    int b = blockIdx.y;
    const float* W = (b == 0) ? W0 : Ws + (size_t)(b - 1) * K * OUTD;
    __nv_bfloat16* ob = out + (size_t)b * OUTD * 2 * K;
    int i = blockIdx.x * blockDim.x + threadIdx.x;
    if (i >= K * OUTD) return;
    int k = i / OUTD, n = i - k * OUTD;
    float v = W[i];
    __nv_bfloat16 h = __float2bfloat16(v);
    float lo = v - __bfloat162float(h);
    __nv_bfloat16* row = ob + (size_t)n * 2 * K;
    row[k] = h;
    row[K + k] = __float2bfloat16(lo);
}

// ============================ HMMA GEMM =====================================
// Logical C[M,128] = A'[M,3*Ka] @ B'[128,3*Ka]^T with the split-3 block
// sequence A:[h|l|h], B:[h|h|l], stored physically as [h|l] (width 2*Ka).
// 128x128 tile/CTA, 256 thr, 8 warps (2m x 4n), BK=64, 3-stage cp.async ring.
// mode 0: branch GEMM. branch 0 -> z2 slice 0 as bf16 [hi|lo] pairs;
//                      branches 1..8 -> H (fp32) with out_norm.
// mode 1: WC/WD GEMM.  branch 0 -> zc; 1 -> zd; scale in_norm[row/9].
#define SROW 144                      // smem row pitch bytes (64 bf16 + 8 pad)
#define ATILE (128 * SROW)            // 18432 B
#define STAGE_SZ (2 * ATILE)          // A + B per stage
#define NSTAGE 3
#define SMEM_TOT (NSTAGE * STAGE_SZ)  // 110592 B

__global__ __launch_bounds__(256, 2)
void mma_gemm(const __nv_bfloat16* __restrict__ A2,
              const __nv_bfloat16* __restrict__ Bbase,
              int Ka, int M,
              __nv_bfloat16* __restrict__ z2out, float* __restrict__ H,
              const float* __restrict__ out_norm, const float* __restrict__ in_norm,
              float* __restrict__ zc, float* __restrict__ zd, int mode)
{
    extern __shared__ __align__(16) char smem[];

    const int tid = threadIdx.x;
    const int wid = tid >> 5, lane = tid & 31;
    const int warpM = wid & 1;          // 0..1 -> 64-row half
    const int warpN = wid >> 1;         // 0..3 -> 32-col slice
    const int branch = blockIdx.y;
    const int rowBase = blockIdx.x * 128;
    const int lda = 2 * Ka;             // physical row width (bf16)
    const int q  = Ka >> 6;             // 64-col chunks per block
    const int nC = 3 * q;               // logical chunks

    const bool toPair = (mode == 0 && branch == 0);
    float* C = nullptr; int ldc = 0; const float* scale = nullptr; int sdiv = 0;
    if (mode == 0) {
        if (branch != 0) { C = H + (size_t)(branch - 1) * NN * OUTD; ldc = OUTD; scale = out_norm; sdiv = 1; }
    } else {
        C = branch ? zd : zc; ldc = OUTD; scale = in_norm; sdiv = NK;
    }
    const __nv_bfloat16* B2 = Bbase + (size_t)branch * OUTD * lda;

    const uint32_t smemBase = smem_u32(smem);
    float acc[4][4][4] = {};            // [mt][nt][frag]

    // ---- stage loader: A,B tiles 128 x 64 bf16; 1024 16B segs each ----------
    auto load_stage = [&](int c, int buf) {
        int blk = c / q, off = c - blk * q;
        int k0A = ((blk & 1)  * q + off) * 64;   // A blocks: h, l, h
        int k0B = ((blk >> 1) * q + off) * 64;   // B blocks: h, h, l
        char* sAb = smem + buf * STAGE_SZ;
        char* sBb = sAb + ATILE;
        #pragma unroll
        for (int i = 0; i < 4; ++i) {
            int idx = tid + i * 256;             // 0..1023
            int r = idx >> 3, c16 = idx & 7;
            int grow = rowBase + r; if (grow > M - 1) grow = M - 1;
            CP_ASYNC16(smem_u32(sAb + r * SROW + c16 * 16),
                       A2 + (size_t)grow * lda + k0A + c16 * 8);
            CP_ASYNC16(smem_u32(sBb + r * SROW + c16 * 16),
                       B2 + (size_t)r * lda + k0B + c16 * 8);
        }
    };

    load_stage(0, 0); CP_COMMIT();
    load_stage(1, 1); CP_COMMIT();

    for (int c = 0; c < nC; ++c) {
        if (c + 1 < nC) CP_WAIT1(); else CP_WAIT0();
        __syncthreads();                          // stage c ready; c-1 consumed
        if (c + 2 < nC) { load_stage(c + 2, (c + 2) % NSTAGE); CP_COMMIT(); }

        const uint32_t sAb = smemBase + (c % NSTAGE) * STAGE_SZ;
        const uint32_t sBb = sAb + ATILE;
        #pragma unroll
        for (int ks = 0; ks < 4; ++ks) {          // four k16 steps per BK=64
            const uint32_t colOff = (ks * 16 + (lane >> 4) * 8) * 2;
            uint32_t a[4][4];
            #pragma unroll
            for (int mt = 0; mt < 4; ++mt)
                ldmx4(a[mt], sAb + (warpM * 64 + mt * 16 + (lane & 15)) * SROW + colOff);
            uint32_t b[2][4];
            #pragma unroll
            for (int nt2 = 0; nt2 < 2; ++nt2)
                ldmx4(b[nt2], sBb + (warpN * 32 + nt2 * 16 + (lane & 15)) * SROW + colOff);
            #pragma unroll
            for (int mt = 0; mt < 4; ++mt)
                #pragma unroll
                for (int nt2 = 0; nt2 < 2; ++nt2) {
                    mma16816(acc[mt][nt2 * 2 + 0], a[mt], b[nt2][0], b[nt2][2]);
                    mma16816(acc[mt][nt2 * 2 + 1], a[mt], b[nt2][1], b[nt2][3]);
                }
        }
    }

    // ---- epilogue: c frag (g=lane>>2, t=lane&3): rows g,g+8; cols 2t,2t+1 ----
    const int g = lane >> 2, t4 = lane & 3;
    #pragma unroll
    for (int mt = 0; mt < 4; ++mt) {
        int row0 = rowBase + warpM * 64 + mt * 16 + g;
        int row1 = row0 + 8;
        if (toPair) {
            // write z slice 0 directly as bf16 [hi | lo] pair rows in z2
            #pragma unroll
            for (int nt = 0; nt < 4; ++nt) {
                int col = warpN * 32 + nt * 8 + 2 * t4;
                #pragma unroll
                for (int half = 0; half < 2; ++half) {
                    int row = half ? row1 : row0;
                    if (row >= M) continue;
                    float c0 = acc[mt][nt][half * 2 + 0];
                    float c1 = acc[mt][nt][half * 2 + 1];
                    __nv_bfloat162 hi = __floats2bfloat162_rn(c0, c1);
                    float l0 = c0 - __bfloat162float(hi.x);
                    float l1 = c1 - __bfloat162float(hi.y);
                    __nv_bfloat162 lo = __floats2bfloat162_rn(l0, l1);
                    __nv_bfloat16* zr = z2out + (size_t)row * NK * 2 * OUTD;
                    *reinterpret_cast<__nv_bfloat162*>(zr + col) = hi;
                    *reinterpret_cast<__nv_bfloat162*>(zr + OUTD + col) = lo;
                }
            }
        } else {
            float s0 = 1.f, s1 = 1.f;
            if (scale) {
                if (row0 < M) s0 = scale[(sdiv == 1) ? row0 : row0 / NK];
                if (row1 < M) s1 = scale[(sdiv == 1) ? row1 : row1 / NK];
            }
            #pragma unroll
            for (int nt = 0; nt < 4; ++nt) {
                int col = warpN * 32 + nt * 8 + 2 * t4;
                if (row0 < M) {
                    float2 v = make_float2(acc[mt][nt][0] * s0, acc[mt][nt][1] * s0);
                    *reinterpret_cast<float2*>(C + (size_t)row0 * ldc + col) = v;
                }
                if (row1 < M) {
                    float2 v = make_float2(acc[mt][nt][2] * s1, acc[mt][nt][3] * s1);
                    *reinterpret_cast<float2*>(C + (size_t)row1 * ldc + col) = v;
                }
            }
        }
    }
}

// ---------------- edge-list build: bucket (sector,src) <- dst ----------------
__global__ __launch_bounds__(256)
void build_lists(const int* __restrict__ rows, const int* __restrict__ cols,
                 int* __restrict__ cnt, int* __restrict__ eidx)
{
    int i = blockIdx.x * blockDim.x + threadIdx.x;
    if (i >= NS * NEP) return;
    int s = i / NEP;
    int src = rows[i];
    int dst = cols[i];
    int b = s * NN + src;
    int slot = atomicAdd(&cnt[b], 1);
    if (slot < EMAX) eidx[(size_t)b * EMAX + slot] = dst;
}

// ---------------- gather aggregation: one warp per (sector,src) --------------
// acc = sum_{dst in list} H[s][dst]; write z2[(src*NK+1+s)] as bf16 [hi|lo].
__global__ __launch_bounds__(256)
void gather_agg(const int* __restrict__ cnt, const int* __restrict__ eidx,
                const float* __restrict__ H, __nv_bfloat16* __restrict__ z2)
{
    int gw   = (blockIdx.x * blockDim.x + threadIdx.x) >> 5;
    int lane = threadIdx.x & 31;
    if (gw >= NS * NN) return;
    int s = gw / NN, src = gw - s * NN;
    int c = cnt[gw]; if (c > EMAX) c = EMAX;
    const int* lst = eidx + (size_t)gw * EMAX;
    const float* Hs = H + (size_t)s * NN * OUTD;

    float4 acc = make_float4(0.f, 0.f, 0.f, 0.f);
    for (int i = 0; i < c; ++i) {
        int dst = lst[i];
        float4 v = *(reinterpret_cast<const float4*>(Hs + (size_t)dst * OUTD) + lane);
        acc.x += v.x; acc.y += v.y; acc.z += v.z; acc.w += v.w;
    }

    __nv_bfloat162 h01 = __floats2bfloat162_rn(acc.x, acc.y);
    __nv_bfloat162 h23 = __floats2bfloat162_rn(acc.z, acc.w);
    __nv_bfloat162 l01 = __floats2bfloat162_rn(acc.x - __bfloat162float(h01.x),
                                               acc.y - __bfloat162float(h01.y));
    __nv_bfloat162 l23 = __floats2bfloat162_rn(acc.z - __bfloat162float(h23.x),
                                               acc.w - __bfloat162float(h23.y));
    __nv_bfloat16* zp = z2 + ((size_t)src * NK + 1 + s) * (2 * OUTD);
    *reinterpret_cast<__nv_bfloat162*>(zp + lane * 4 + 0) = h01;
    *reinterpret_cast<__nv_bfloat162*>(zp + lane * 4 + 2) = h23;
    *reinterpret_cast<__nv_bfloat162*>(zp + OUTD + lane * 4 + 0) = l01;
    *reinterpret_cast<__nv_bfloat162*>(zp + OUTD + lane * 4 + 2) = l23;
}

// ---------------- per-node interaction (verified) ----------------------------
__global__ __launch_bounds__(128)
void interact(const float* __restrict__ zc, const float* __restrict__ zd,
              const float* __restrict__ gw, const float* __restrict__ gb,
              float* __restrict__ out)
{
    const int n = blockIdx.x;
    const int t = threadIdx.x;
    __shared__ float sc[NK][OUTD];
    __shared__ float sd[NK][OUTD];
    __shared__ float ac[NK][NK];
    __shared__ float ad[NK][NK];
    __shared__ float red[4];
    __shared__ float s_beta;

    const float* zcn = zc + (size_t)n * NK * OUTD;
    const float* zdn = zd + (size_t)n * NK * OUTD;
    #pragma unroll
    for (int r = 0; r < NK; ++r) {
        sc[r][t] = zcn[r * OUTD + t];
        sd[r][t] = zdn[r * OUTD + t];
    }
    __syncthreads();

    const int warp = t >> 5, lane = t & 31;
    for (int d = warp; d < 162; d += 4) {
        int which = (d >= 81);
        int p = which ? d - 81 : d;
        int k = p / 9, j = p - 9 * k;
        const float* a = which ? sd[k] : sc[k];
        const float* b = which ? sd[j] : sc[j];
        float part = 0.f;
        #pragma unroll
        for (int o = 0; o < 4; ++o) part += a[lane + 32 * o] * b[lane + 32 * o];
        #pragma unroll
        for (int off = 16; off; off >>= 1)
            part += __shfl_down_sync(0xffffffffu, part, off);
        if (lane == 0) { if (which) ad[k][j] = part; else ac[k][j] = part; }
    }
    __syncthreads();

    if (t < 9) {
        float row[NK]; float m = -1e30f;
        #pragma unroll
        for (int j = 0; j < NK; ++j) { row[j] = ac[t][j]; m = fmaxf(m, row[j]); }
        float ssum = 0.f;
        #pragma unroll
        for (int j = 0; j < NK; ++j) { row[j] = expf(row[j] - m); ssum += row[j]; }
        float inv = 1.f / ssum;
        #pragma unroll
        for (int j = 0; j < NK; ++j) ac[t][j] = row[j] * inv;
    } else if (t >= 16 && t < 25) {
        int k = t - 16;
        float q = ad[k][k];
        float row[NK]; float m = -1e30f;
        #pragma unroll
        for (int j = 0; j < NK; ++j) { row[j] = q - ad[k][j]; m = fmaxf(m, row[j]); }
        float ssum = 0.f;
        #pragma unroll
        for (int j = 0; j < NK; ++j) { row[j] = expf(row[j] - m); ssum += row[j]; }
        float inv = 1.f / ssum;
        #pragma unroll
        for (int j = 0; j < NK; ++j) ad[k][j] = row[j] * inv;
    }
    __syncthreads();

    float zcom[NK], zdis[NK];
    #pragma unroll
    for (int k = 0; k < NK; ++k) {
        float a0 = 0.f, a1 = 0.f;
        #pragma unroll
        for (int j = 0; j < NK; ++j) {
            a0 += ac[k][j] * sc[j][t];
            a1 += ad[k][j] * sd[j][t];
        }
        zcom[k] = a0;
        zdis[k] = sd[k][t] - a1;
    }

    float gp = 0.f;
    #pragma unroll
    for (int k = 0; k < NK; ++k)
        gp += zcom[k] * gw[k * OUTD + t] + zdis[k] * gw[NK * OUTD + k * OUTD + t];
    #pragma unroll
    for (int off = 16; off; off >>= 1)
        gp += __shfl_down_sync(0xffffffffu, gp, off);
    if (lane == 0) red[warp] = gp;
    __syncthreads();
    if (t == 0) {
        float tot = red[0] + red[1] + red[2] + red[3] + gb[0];
        s_beta = 1.f / (1.f + expf(-tot));
    }
    __syncthreads();
    const float beta = s_beta;

    float* op = out + (size_t)n * (NK * OUTD);
    #pragma unroll
    for (int k = 0; k < NK; ++k)
        op[k * OUTD + t] = beta * zcom[k] + (1.f - beta) * zdis[k];
}

// ---------------- launch ------------------------------------------------------
extern "C" void kernel_launch(void* const* d_in, const int* in_sizes, int n_in,
                              void* d_out, int out_size)
{
    const float* x        = (const float*)d_in[0];
    const float* W_self   = (const float*)d_in[1];
    const float* W_sect   = (const float*)d_in[2];
    const float* WC       = (const float*)d_in[3];
    const float* WD       = (const float*)d_in[4];
    const float* gate_w   = (const float*)d_in[5];
    const float* gate_b   = (const float*)d_in[6];
    const float* out_norm = (const float*)d_in[7];
    const float* in_norm  = (const float*)d_in[8];
    const int*   rows     = (const int*)d_in[9];
    const int*   cols     = (const int*)d_in[10];
    float* out = (float*)d_out;

    float *H, *zc, *zd;
    __nv_bfloat16 *x2, *z2, *w1t, *w2t;
    int *cnt, *eidx;
    cudaGetSymbolAddress((void**)&H,    d_H);
    cudaGetSymbolAddress((void**)&zc,   d_zc);
    cudaGetSymbolAddress((void**)&zd,   d_zd);
    cudaGetSymbolAddress((void**)&x2,   d_x2);
    cudaGetSymbolAddress((void**)&z2,   d_z2);
    cudaGetSymbolAddress((void**)&w1t,  d_w1t);
    cudaGetSymbolAddress((void**)&w2t,  d_w2t);
    cudaGetSymbolAddress((void**)&cnt,  d_cnt);
    cudaGetSymbolAddress((void**)&eidx, d_eidx);

    // allow >48KB dynamic smem for the GEMM (idempotent; host-side only)
    cudaFuncSetAttribute(mma_gemm, cudaFuncAttributeMaxDynamicSharedMemorySize, SMEM_TOT);

    // 1) zero bucket counters; build per-(sector,src) edge lists
    cudaMemsetAsync(cnt, 0, sizeof(int) * (size_t)NS * NN, 0);
    build_lists<<<(NS * NEP + 255) / 256, 256>>>(rows, cols, cnt, eidx);

    // 2) split-bf16 [hi|lo] conversions (x, weights)
    conv_pair<<<(NN * IND + 255) / 256, 256>>>(x, x2, NN, IND);
    conv_w<<<dim3((IND * OUTD + 255) / 256, NK), 256>>>(W_self, W_sect, w1t, IND);
    conv_w<<<dim3((OUTD * OUTD + 255) / 256, 2), 256>>>(WC, WD, w2t, OUTD);

    // 3) batched branch GEMMs (9 branches, Ka=256); branch 0 writes z2 directly
    mma_gemm<<<dim3((NN + 127) / 128, NK), 256, SMEM_TOT>>>(
        x2, w1t, IND, NN, z2, H, out_norm, in_norm, zc, zd, 0);

    // 4) gather aggregation -> z2 slices 1..8 (bf16 pairs, no atomics on data)
    gather_agg<<<(NS * NN * 32 + 255) / 256, 256>>>(cnt, eidx, H, z2);

    // 5) batched WC/WD GEMMs (Ka = 128) from z2
    mma_gemm<<<dim3((NN * NK + 127) / 128, 2), 256, SMEM_TOT>>>(
        z2, w2t, OUTD, NN * NK, z2, H, out_norm, in_norm, zc, zd, 1);

    // 6) per-node interaction + gate
    interact<<<NN, 128>>>(zc, zd, gate_w, gate_b, out);
}

// round 7
// speedup vs baseline: 2.1845x; 1.0014x over previous
#include <cuda_runtime.h>
#include <cuda_bf16.h>
#include <cstdint>

// Problem constants (fixed by the dataset)
#define NN   20000   // nodes
#define IND  256     // in_dim
#define OUTD 128     // out_dim
#define NS   8       // num sectors
#define NK   9       // K = S+1
#define NEP  40000   // edges per sector
#define EMAX 64      // per-(sector,src) edge-list capacity (Poisson(2) degrees)

// ---------------- scratch (device globals; no allocations allowed) ----------
__device__ float d_H   [(size_t)NS * NN * OUTD];            // per-sector H (out_norm applied)
__device__ float d_zc  [(size_t)NN * NK * OUTD];            // (z*in_norm) @ WC
__device__ float d_zd  [(size_t)NN * NK * OUTD];            // (z*in_norm) @ WD
// split-bf16 operands stored compactly as [hi | lo]; the GEMM remaps the
// logical 3-block sequence A:[h|l|h], B:[h|h|l] onto these.
__device__ __nv_bfloat16 d_x2 [(size_t)NN * 2 * IND];         // [N, 512]
__device__ __nv_bfloat16 d_z2 [(size_t)NN * NK * 2 * OUTD];   // [N*K, 256]
__device__ __nv_bfloat16 d_w1t[(size_t)NK * OUTD * 2 * IND];  // [9][128,512]
__device__ __nv_bfloat16 d_w2t[(size_t)2  * OUTD * 2 * OUTD]; // [2][128,256]
// CSR-ish fixed-capacity edge lists, rebuilt every call
__device__ int d_cnt [(size_t)NS * NN];
__device__ int d_eidx[(size_t)NS * NN * EMAX];

// ============================ PTX helpers ====================================
__device__ __forceinline__ uint32_t smem_u32(const void* p) {
    uint32_t a;
    asm("{ .reg .u64 t; cvta.to.shared.u64 t, %1; cvt.u32.u64 %0, t; }" : "=r"(a) : "l"(p));
    return a;
}
__device__ __forceinline__ void ldmx4(uint32_t* r, uint32_t addr) {
    asm volatile("ldmatrix.sync.aligned.m8n8.x4.shared.b16 {%0,%1,%2,%3}, [%4];"
        : "=r"(r[0]), "=r"(r[1]), "=r"(r[2]), "=r"(r[3]) : "r"(addr));
}
__device__ __forceinline__ void mma16816(float* c, const uint32_t* a, uint32_t b0, uint32_t b1) {
    asm volatile("mma.sync.aligned.m16n8k16.row.col.f32.bf16.bf16.f32 "
        "{%0,%1,%2,%3}, {%4,%5,%6,%7}, {%8,%9}, {%0,%1,%2,%3};"
        : "+f"(c[0]), "+f"(c[1]), "+f"(c[2]), "+f"(c[3])
        : "r"(a[0]), "r"(a[1]), "r"(a[2]), "r"(a[3]), "r"(b0), "r"(b1));
}
#define CP_ASYNC16(sp, gp) \
    asm volatile("cp.async.cg.shared.global [%0], [%1], 16;" :: "r"(sp), "l"(gp))
#define CP_COMMIT() asm volatile("cp.async.commit_group;" ::: "memory")
#define CP_WAIT1()  asm volatile("cp.async.wait_group 1;" ::: "memory")
#define CP_WAIT0()  asm volatile("cp.async.wait_group 0;" ::: "memory")

// ============================ conversion kernels =============================
// x fp32 [NN, IND] -> [hi | lo] (row stride 2*IND); also zeroes cnt buckets.
__global__ __launch_bounds__(256)
void conv_x(const float* __restrict__ in, __nv_bfloat16* __restrict__ out,
            int* __restrict__ cnt)
{
    int i = blockIdx.x * blockDim.x + threadIdx.x;
    if (i < NS * NN) cnt[i] = 0;
    if (i >= NN * IND) return;
    int r = i / IND, c = i - r * IND;
    float v = in[i];
    __nv_bfloat16 h = __float2bfloat16(v);
    float lo = v - __bfloat162float(h);
    __nv_bfloat16* op = out + (size_t)r * 2 * IND;
    op[c] = h;
    op[IND + c] = __float2bfloat16(lo);
}

// all 11 weight matrices -> transposed [hi | lo]
// b 0..8: W_self/W_sect (K=IND) -> w1t ; b 9..10: WC/WD (K=OUTD) -> w2t
__global__ __launch_bounds__(256)
void conv_w_all(const float* __restrict__ W_self, const float* __restrict__ W_sect,
                const float* __restrict__ WC, const float* __restrict__ WD,
                __nv_bfloat16* __restrict__ w1t, __nv_bfloat16* __restrict__ w2t)
{
    int b = blockIdx.y;
    const float* W; __nv_bfloat16* ob; int K;
    if (b == 0)      { W = W_self; ob = w1t; K = IND; }
    else if (b < 9)  { W = W_sect + (size_t)(b - 1) * IND * OUTD; ob = w1t + (size_t)b * OUTD * 2 * IND; K = IND; }
    else             { W = (b == 9) ? WC : WD; ob = w2t + (size_t)(b - 9) * OUTD * 2 * OUTD; K = OUTD; }
    int i = blockIdx.x * blockDim.x + threadIdx.x;
    if (i >= K * OUTD) return;
    int k = i / OUTD, n = i - k * OUTD;
    float v = W[i];
    __nv_bfloat16 h = __float2bfloat16(v);
    float lo = v - __bfloat162float(h);
    __nv_bfloat16* row = ob + (size_t)n * 2 * K;
    row[k] = h;
    row[K + k] = __float2bfloat16(lo);
}

// ============================ HMMA GEMM =====================================
// Logical C[M,128] = A'[M,3*Ka] @ B'[128,3*Ka]^T with the split-3 block
// sequence A:[h|l|h], B:[h|h|l], stored physically as [h|l] (width 2*Ka).
// 128x128 tile/CTA, 256 thr, 8 warps (2m x 4n), BK=64, 3-stage cp.async ring.
// mode 0: grid (tiles, 9). branch 0 -> z2 slice 0 (bf16 pairs); 1..8 -> H fp32.
// mode 1: grid (2*tiles). branch = blockIdx.x&1 (WC/WD interleaved for L2
//         reuse of the shared A tile); -> zc / zd with in_norm.
#define SROW 144                      // smem row pitch bytes (64 bf16 + 8 pad)
#define ATILE (128 * SROW)            // 18432 B
#define STAGE_SZ (2 * ATILE)          // A + B per stage
#define NSTAGE 3
#define SMEM_TOT (NSTAGE * STAGE_SZ)  // 110592 B

__global__ __launch_bounds__(256, 2)
void mma_gemm(const __nv_bfloat16* __restrict__ A2,
              const __nv_bfloat16* __restrict__ Bbase,
              int Ka, int M,
              __nv_bfloat16* __restrict__ z2out, float* __restrict__ H,
              const float* __restrict__ out_norm, const float* __restrict__ in_norm,
              float* __restrict__ zc, float* __restrict__ zd, int mode)
{
    extern __shared__ __align__(16) char smem[];

    const int tid = threadIdx.x;
    const int wid = tid >> 5, lane = tid & 31;
    const int warpM = wid & 1;          // 0..1 -> 64-row half
    const int warpN = wid >> 1;         // 0..3 -> 32-col slice
    int branch, rowBase;
    if (mode == 0) { branch = blockIdx.y; rowBase = blockIdx.x * 128; }
    else           { branch = blockIdx.x & 1; rowBase = (blockIdx.x >> 1) * 128; }
    const int lda = 2 * Ka;             // physical row width (bf16)
    const int q  = Ka >> 6;             // 64-col chunks per block
    const int nC = 3 * q;               // logical chunks

    const bool toPair = (mode == 0 && branch == 0);
    float* C = nullptr; int ldc = 0; const float* scale = nullptr; int sdiv = 0;
    if (mode == 0) {
        if (branch != 0) { C = H + (size_t)(branch - 1) * NN * OUTD; ldc = OUTD; scale = out_norm; sdiv = 1; }
    } else {
        C = branch ? zd : zc; ldc = OUTD; scale = in_norm; sdiv = NK;
    }
    const __nv_bfloat16* B2 = Bbase + (size_t)branch * OUTD * lda;

    const uint32_t smemBase = smem_u32(smem);
    float acc[4][4][4] = {};            // [mt][nt][frag]

    // ---- stage loader: A,B tiles 128 x 64 bf16; 1024 16B segs each ----------
    auto load_stage = [&](int c, int buf) {
        int blk = c / q, off = c - blk * q;
        int k0A = ((blk & 1)  * q + off) * 64;   // A blocks: h, l, h
        int k0B = ((blk >> 1) * q + off) * 64;   // B blocks: h, h, l
        char* sAb = smem + buf * STAGE_SZ;
        char* sBb = sAb + ATILE;
        #pragma unroll
        for (int i = 0; i < 4; ++i) {
            int idx = tid + i * 256;             // 0..1023
            int r = idx >> 3, c16 = idx & 7;
            int grow = rowBase + r; if (grow > M - 1) grow = M - 1;
            CP_ASYNC16(smem_u32(sAb + r * SROW + c16 * 16),
                       A2 + (size_t)grow * lda + k0A + c16 * 8);
            CP_ASYNC16(smem_u32(sBb + r * SROW + c16 * 16),
                       B2 + (size_t)r * lda + k0B + c16 * 8);
        }
    };

    load_stage(0, 0); CP_COMMIT();
    load_stage(1, 1); CP_COMMIT();

    for (int c = 0; c < nC; ++c) {
        if (c + 1 < nC) CP_WAIT1(); else CP_WAIT0();
        __syncthreads();                          // stage c ready; c-1 consumed
        if (c + 2 < nC) { load_stage(c + 2, (c + 2) % NSTAGE); CP_COMMIT(); }

        const uint32_t sAb = smemBase + (c % NSTAGE) * STAGE_SZ;
        const uint32_t sBb = sAb + ATILE;
        #pragma unroll
        for (int ks = 0; ks < 4; ++ks) {          // four k16 steps per BK=64
            const uint32_t colOff = (ks * 16 + (lane >> 4) * 8) * 2;
            uint32_t a[4][4];
            #pragma unroll
            for (int mt = 0; mt < 4; ++mt)
                ldmx4(a[mt], sAb + (warpM * 64 + mt * 16 + (lane & 15)) * SROW + colOff);
            uint32_t b[2][4];
            #pragma unroll
            for (int nt2 = 0; nt2 < 2; ++nt2)
                ldmx4(b[nt2], sBb + (warpN * 32 + nt2 * 16 + (lane & 15)) * SROW + colOff);
            #pragma unroll
            for (int mt = 0; mt < 4; ++mt)
                #pragma unroll
                for (int nt2 = 0; nt2 < 2; ++nt2) {
                    mma16816(acc[mt][nt2 * 2 + 0], a[mt], b[nt2][0], b[nt2][2]);
                    mma16816(acc[mt][nt2 * 2 + 1], a[mt], b[nt2][1], b[nt2][3]);
                }
        }
    }

    // ---- epilogue: c frag (g=lane>>2, t=lane&3): rows g,g+8; cols 2t,2t+1 ----
    const int g = lane >> 2, t4 = lane & 3;
    #pragma unroll
    for (int mt = 0; mt < 4; ++mt) {
        int row0 = rowBase + warpM * 64 + mt * 16 + g;
        int row1 = row0 + 8;
        if (toPair) {
            // write z slice 0 directly as bf16 [hi | lo] pair rows in z2
            #pragma unroll
            for (int nt = 0; nt < 4; ++nt) {
                int col = warpN * 32 + nt * 8 + 2 * t4;
                #pragma unroll
                for (int half = 0; half < 2; ++half) {
                    int row = half ? row1 : row0;
                    if (row >= M) continue;
                    float c0 = acc[mt][nt][half * 2 + 0];
                    float c1 = acc[mt][nt][half * 2 + 1];
                    __nv_bfloat162 hi = __floats2bfloat162_rn(c0, c1);
                    float l0 = c0 - __bfloat162float(hi.x);
                    float l1 = c1 - __bfloat162float(hi.y);
                    __nv_bfloat162 lo = __floats2bfloat162_rn(l0, l1);
                    __nv_bfloat16* zr = z2out + (size_t)row * NK * 2 * OUTD;
                    *reinterpret_cast<__nv_bfloat162*>(zr + col) = hi;
                    *reinterpret_cast<__nv_bfloat162*>(zr + OUTD + col) = lo;
                }
            }
        } else {
            float s0 = 1.f, s1 = 1.f;
            if (scale) {
                if (row0 < M) s0 = scale[(sdiv == 1) ? row0 : row0 / NK];
                if (row1 < M) s1 = scale[(sdiv == 1) ? row1 : row1 / NK];
            }
            #pragma unroll
            for (int nt = 0; nt < 4; ++nt) {
                int col = warpN * 32 + nt * 8 + 2 * t4;
                if (row0 < M) {
                    float2 v = make_float2(acc[mt][nt][0] * s0, acc[mt][nt][1] * s0);
                    *reinterpret_cast<float2*>(C + (size_t)row0 * ldc + col) = v;
                }
                if (row1 < M) {
                    float2 v = make_float2(acc[mt][nt][2] * s1, acc[mt][nt][3] * s1);
                    *reinterpret_cast<float2*>(C + (size_t)row1 * ldc + col) = v;
                }
            }
        }
    }
}

// ---------------- edge-list build: bucket (sector,src) <- dst ----------------
__global__ __launch_bounds__(256)
void build_lists(const int* __restrict__ rows, const int* __restrict__ cols,
                 int* __restrict__ cnt, int* __restrict__ eidx)
{
    int i = blockIdx.x * blockDim.x + threadIdx.x;
    if (i >= NS * NEP) return;
    int s = i / NEP;
    int src = rows[i];
    int dst = cols[i];
    int b = s * NN + src;
    int slot = atomicAdd(&cnt[b], 1);
    if (slot < EMAX) eidx[(size_t)b * EMAX + slot] = dst;
}

// ---------------- gather aggregation: one warp per (sector,src) --------------
// acc = sum_{dst in list} H[s][dst]; write z2[(src*NK+1+s)] as bf16 [hi|lo].
__global__ __launch_bounds__(256)
void gather_agg(const int* __restrict__ cnt, const int* __restrict__ eidx,
                const float* __restrict__ H, __nv_bfloat16* __restrict__ z2)
{
    int gw   = (blockIdx.x * blockDim.x + threadIdx.x) >> 5;
    int lane = threadIdx.x & 31;
    if (gw >= NS * NN) return;
    int s = gw / NN, src = gw - s * NN;
    int c = cnt[gw]; if (c > EMAX) c = EMAX;
    const int* lst = eidx + (size_t)gw * EMAX;
    const float* Hs = H + (size_t)s * NN * OUTD;

    float4 acc = make_float4(0.f, 0.f, 0.f, 0.f);
    for (int i = 0; i < c; ++i) {
        int dst = lst[i];
        float4 v = *(reinterpret_cast<const float4*>(Hs + (size_t)dst * OUTD) + lane);
        acc.x += v.x; acc.y += v.y; acc.z += v.z; acc.w += v.w;
    }

    __nv_bfloat162 h01 = __floats2bfloat162_rn(acc.x, acc.y);
    __nv_bfloat162 h23 = __floats2bfloat162_rn(acc.z, acc.w);
    __nv_bfloat162 l01 = __floats2bfloat162_rn(acc.x - __bfloat162float(h01.x),
                                               acc.y - __bfloat162float(h01.y));
    __nv_bfloat162 l23 = __floats2bfloat162_rn(acc.z - __bfloat162float(h23.x),
                                               acc.w - __bfloat162float(h23.y));
    __nv_bfloat16* zp = z2 + ((size_t)src * NK + 1 + s) * (2 * OUTD);
    *reinterpret_cast<__nv_bfloat162*>(zp + lane * 4 + 0) = h01;
    *reinterpret_cast<__nv_bfloat162*>(zp + lane * 4 + 2) = h23;
    *reinterpret_cast<__nv_bfloat162*>(zp + OUTD + lane * 4 + 0) = l01;
    *reinterpret_cast<__nv_bfloat162*>(zp + OUTD + lane * 4 + 2) = l23;
}

// ---------------- per-node interaction (verified) ----------------------------
__global__ __launch_bounds__(128)
void interact(const float* __restrict__ zc, const float* __restrict__ zd,
              const float* __restrict__ gw, const float* __restrict__ gb,
              float* __restrict__ out)
{
    const int n = blockIdx.x;
    const int t = threadIdx.x;
    __shared__ float sc[NK][OUTD];
    __shared__ float sd[NK][OUTD];
    __shared__ float ac[NK][NK];
    __shared__ float ad[NK][NK];
    __shared__ float red[4];
    __shared__ float s_beta;

    const float* zcn = zc + (size_t)n * NK * OUTD;
    const float* zdn = zd + (size_t)n * NK * OUTD;
    #pragma unroll
    for (int r = 0; r < NK; ++r) {
        sc[r][t] = zcn[r * OUTD + t];
        sd[r][t] = zdn[r * OUTD + t];
    }
    __syncthreads();

    const int warp = t >> 5, lane = t & 31;
    for (int d = warp; d < 162; d += 4) {
        int which = (d >= 81);
        int p = which ? d - 81 : d;
        int k = p / 9, j = p - 9 * k;
        const float* a = which ? sd[k] : sc[k];
        const float* b = which ? sd[j] : sc[j];
        float part = 0.f;
        #pragma unroll
        for (int o = 0; o < 4; ++o) part += a[lane + 32 * o] * b[lane + 32 * o];
        #pragma unroll
        for (int off = 16; off; off >>= 1)
            part += __shfl_down_sync(0xffffffffu, part, off);
        if (lane == 0) { if (which) ad[k][j] = part; else ac[k][j] = part; }
    }
    __syncthreads();

    if (t < 9) {
        float row[NK]; float m = -1e30f;
        #pragma unroll
        for (int j = 0; j < NK; ++j) { row[j] = ac[t][j]; m = fmaxf(m, row[j]); }
        float ssum = 0.f;
        #pragma unroll
        for (int j = 0; j < NK; ++j) { row[j] = expf(row[j] - m); ssum += row[j]; }
        float inv = 1.f / ssum;
        #pragma unroll
        for (int j = 0; j < NK; ++j) ac[t][j] = row[j] * inv;
    } else if (t >= 16 && t < 25) {
        int k = t - 16;
        float q = ad[k][k];
        float row[NK]; float m = -1e30f;
        #pragma unroll
        for (int j = 0; j < NK; ++j) { row[j] = q - ad[k][j]; m = fmaxf(m, row[j]); }
        float ssum = 0.f;
        #pragma unroll
        for (int j = 0; j < NK; ++j) { row[j] = expf(row[j] - m); ssum += row[j]; }
        float inv = 1.f / ssum;
        #pragma unroll
        for (int j = 0; j < NK; ++j) ad[k][j] = row[j] * inv;
    }
    __syncthreads();

    float zcom[NK], zdis[NK];
    #pragma unroll
    for (int k = 0; k < NK; ++k) {
        float a0 = 0.f, a1 = 0.f;
        #pragma unroll
        for (int j = 0; j < NK; ++j) {
            a0 += ac[k][j] * sc[j][t];
            a1 += ad[k][j] * sd[j][t];
        }
        zcom[k] = a0;
        zdis[k] = sd[k][t] - a1;
    }

    float gp = 0.f;
    #pragma unroll
    for (int k = 0; k < NK; ++k)
        gp += zcom[k] * gw[k * OUTD + t] + zdis[k] * gw[NK * OUTD + k * OUTD + t];
    #pragma unroll
    for (int off = 16; off; off >>= 1)
        gp += __shfl_down_sync(0xffffffffu, gp, off);
    if (lane == 0) red[warp] = gp;
    __syncthreads();
    if (t == 0) {
        float tot = red[0] + red[1] + red[2] + red[3] + gb[0];
        s_beta = 1.f / (1.f + expf(-tot));
    }
    __syncthreads();
    const float beta = s_beta;

    float* op = out + (size_t)n * (NK * OUTD);
    #pragma unroll
    for (int k = 0; k < NK; ++k)
        op[k * OUTD + t] = beta * zcom[k] + (1.f - beta) * zdis[k];
}

// ---------------- launch ------------------------------------------------------
extern "C" void kernel_launch(void* const* d_in, const int* in_sizes, int n_in,
                              void* d_out, int out_size)
{
    const float* x        = (const float*)d_in[0];
    const float* W_self   = (const float*)d_in[1];
    const float* W_sect   = (const float*)d_in[2];
    const float* WC       = (const float*)d_in[3];
    const float* WD       = (const float*)d_in[4];
    const float* gate_w   = (const float*)d_in[5];
    const float* gate_b   = (const float*)d_in[6];
    const float* out_norm = (const float*)d_in[7];
    const float* in_norm  = (const float*)d_in[8];
    const int*   rows     = (const int*)d_in[9];
    const int*   cols     = (const int*)d_in[10];
    float* out = (float*)d_out;

    float *H, *zc, *zd;
    __nv_bfloat16 *x2, *z2, *w1t, *w2t;
    int *cnt, *eidx;
    cudaGetSymbolAddress((void**)&H,    d_H);
    cudaGetSymbolAddress((void**)&zc,   d_zc);
    cudaGetSymbolAddress((void**)&zd,   d_zd);
    cudaGetSymbolAddress((void**)&x2,   d_x2);
    cudaGetSymbolAddress((void**)&z2,   d_z2);
    cudaGetSymbolAddress((void**)&w1t,  d_w1t);
    cudaGetSymbolAddress((void**)&w2t,  d_w2t);
    cudaGetSymbolAddress((void**)&cnt,  d_cnt);
    cudaGetSymbolAddress((void**)&eidx, d_eidx);

    // allow >48KB dynamic smem for the GEMM (idempotent; host-side only)
    cudaFuncSetAttribute(mma_gemm, cudaFuncAttributeMaxDynamicSharedMemorySize, SMEM_TOT);

    // (0) convert x -> [hi|lo]; also zeroes the bucket counters
    conv_x<<<(NN * IND + 255) / 256, 256>>>(x, x2, cnt);

    // (1) build per-(sector,src) edge lists
    build_lists<<<(NS * NEP + 255) / 256, 256>>>(rows, cols, cnt, eidx);

    // (2) all weight conversions in one launch (9 x w1t, 2 x w2t)
    conv_w_all<<<dim3((IND * OUTD + 255) / 256, 11), 256>>>(W_self, W_sect, WC, WD, w1t, w2t);

    // (3) batched branch GEMMs (9 branches, Ka=256); branch 0 writes z2 directly
    mma_gemm<<<dim3((NN + 127) / 128, NK), 256, SMEM_TOT>>>(
        x2, w1t, IND, NN, z2, H, out_norm, in_norm, zc, zd, 0);

    // (4) gather aggregation -> z2 slices 1..8   [profiled slot]
    gather_agg<<<(NS * NN * 32 + 255) / 256, 256>>>(cnt, eidx, H, z2);

    // (5) WC/WD GEMMs, branch interleaved in grid.x for A-tile L2 reuse
    mma_gemm<<<dim3(2 * ((NN * NK + 127) / 128), 1), 256, SMEM_TOT>>>(
        z2, w2t, OUTD, NN * NK, z2, H, out_norm, in_norm, zc, zd, 1);

    // (6) per-node interaction + gate
    interact<<<NN, 128>>>(zc, zd, gate_w, gate_b, out);
}

// round 8
// speedup vs baseline: 2.5275x; 1.1570x over previous
#include <cuda_runtime.h>
#include <cuda_fp16.h>
#include <cstdint>

// Problem constants (fixed by the dataset)
#define NN   20000   // nodes
#define IND  256     // in_dim
#define OUTD 128     // out_dim
#define NS   8       // num sectors
#define NK   9       // K = S+1
#define NEP  40000   // edges per sector
#define EMAX 64      // per-(sector,src) edge-list capacity (Poisson(2) degrees)

// ---------------- scratch (device globals; no allocations allowed) ----------
__device__ float d_H   [(size_t)NS * NN * OUTD];            // per-sector H (out_norm applied)
__device__ float d_zc  [(size_t)NN * NK * OUTD];            // (z*in_norm) @ WC
__device__ float d_zd  [(size_t)NN * NK * OUTD];            // (z*in_norm) @ WD
// fp16 split-2 operands, symmetric [hi | lo] stacked along K (Kd = 2*Ka)
__device__ __half d_x2 [(size_t)NN * 2 * IND];              // [N, 512]
__device__ __half d_z2 [(size_t)NN * NK * 2 * OUTD];        // [N*K, 256]
__device__ __half d_w1t[(size_t)NK * OUTD * 2 * IND];       // [9][128,512]
__device__ __half d_w2t[(size_t)2  * OUTD * 2 * OUTD];      // [2][128,256]
// CSR-ish fixed-capacity edge lists, rebuilt every call
__device__ int d_cnt [(size_t)NS * NN];
__device__ int d_eidx[(size_t)NS * NN * EMAX];

// ============================ PTX helpers ====================================
__device__ __forceinline__ uint32_t smem_u32(const void* p) {
    uint32_t a;
    asm("{ .reg .u64 t; cvta.to.shared.u64 t, %1; cvt.u32.u64 %0, t; }" : "=r"(a) : "l"(p));
    return a;
}
__device__ __forceinline__ void ldmx4(uint32_t* r, uint32_t addr) {
    asm volatile("ldmatrix.sync.aligned.m8n8.x4.shared.b16 {%0,%1,%2,%3}, [%4];"
        : "=r"(r[0]), "=r"(r[1]), "=r"(r[2]), "=r"(r[3]) : "r"(addr));
}
__device__ __forceinline__ void mma16816(float* c, const uint32_t* a, uint32_t b0, uint32_t b1) {
    asm volatile("mma.sync.aligned.m16n8k16.row.col.f32.f16.f16.f32 "
        "{%0,%1,%2,%3}, {%4,%5,%6,%7}, {%8,%9}, {%0,%1,%2,%3};"
        : "+f"(c[0]), "+f"(c[1]), "+f"(c[2]), "+f"(c[3])
        : "r"(a[0]), "r"(a[1]), "r"(a[2]), "r"(a[3]), "r"(b0), "r"(b1));
}
#define CP_ASYNC16(sp, gp) \
    asm volatile("cp.async.cg.shared.global [%0], [%1], 16;" :: "r"(sp), "l"(gp))
#define CP_COMMIT() asm volatile("cp.async.commit_group;" ::: "memory")
#define CP_WAIT1()  asm volatile("cp.async.wait_group 1;" ::: "memory")
#define CP_WAIT0()  asm volatile("cp.async.wait_group 0;" ::: "memory")

// ============================ conversion kernels =============================
// x fp32 [NN, IND] -> fp16 [hi | lo] (row stride 2*IND); also zeroes cnt.
__global__ __launch_bounds__(256)
void conv_x(const float* __restrict__ in, __half* __restrict__ out,
            int* __restrict__ cnt)
{
    int i = blockIdx.x * blockDim.x + threadIdx.x;
    if (i < NS * NN) cnt[i] = 0;
    if (i >= NN * IND) return;
    int r = i / IND, c = i - r * IND;
    float v = in[i];
    __half h = __float2half_rn(v);
    float lo = v - __half2float(h);
    __half* op = out + (size_t)r * 2 * IND;
    op[c] = h;
    op[IND + c] = __float2half_rn(lo);
}

// all 11 weight matrices -> transposed fp16 [hi | lo]
// b 0..8: W_self/W_sect (K=IND) -> w1t ; b 9..10: WC/WD (K=OUTD) -> w2t
__global__ __launch_bounds__(256)
void conv_w_all(const float* __restrict__ W_self, const float* __restrict__ W_sect,
                const float* __restrict__ WC, const float* __restrict__ WD,
                __half* __restrict__ w1t, __half* __restrict__ w2t)
{
    int b = blockIdx.y;
    const float* W; __half* ob; int K;
    if (b == 0)      { W = W_self; ob = w1t; K = IND; }
    else if (b < 9)  { W = W_sect + (size_t)(b - 1) * IND * OUTD; ob = w1t + (size_t)b * OUTD * 2 * IND; K = IND; }
    else             { W = (b == 9) ? WC : WD; ob = w2t + (size_t)(b - 9) * OUTD * 2 * OUTD; K = OUTD; }
    int i = blockIdx.x * blockDim.x + threadIdx.x;
    if (i >= K * OUTD) return;
    int k = i / OUTD, n = i - k * OUTD;
    float v = W[i];
    __half h = __float2half_rn(v);
    float lo = v - __half2float(h);
    __half* row = ob + (size_t)n * 2 * K;
    row[k] = h;
    row[K + k] = __float2half_rn(lo);
}

// ============================ shared GEMM pieces =============================
#define SROW 144                      // smem row pitch bytes (64 fp16 cols + pad)
#define ATILE (128 * SROW)            // 18432 B
#define NSTAGE0 3
#define SMEM_TOT (NSTAGE0 * 2 * ATILE)   // 110592 B (both kernels use this size)

// warp-level MMA step on one 64-col chunk (4 k16 steps)
__device__ __forceinline__ void chunk_mma(uint32_t sAb, uint32_t sBb,
                                          int warpM, int warpN, int lane,
                                          float acc[4][4][4])
{
    #pragma unroll
    for (int ks = 0; ks < 4; ++ks) {
        const uint32_t colOff = (ks * 16 + (lane >> 4) * 8) * 2;
        uint32_t a[4][4];
        #pragma unroll
        for (int mt = 0; mt < 4; ++mt)
            ldmx4(a[mt], sAb + (warpM * 64 + mt * 16 + (lane & 15)) * SROW + colOff);
        uint32_t b[2][4];
        #pragma unroll
        for (int nt2 = 0; nt2 < 2; ++nt2)
            ldmx4(b[nt2], sBb + (warpN * 32 + nt2 * 16 + (lane & 15)) * SROW + colOff);
        #pragma unroll
        for (int mt = 0; mt < 4; ++mt)
            #pragma unroll
            for (int nt2 = 0; nt2 < 2; ++nt2) {
                mma16816(acc[mt][nt2 * 2 + 0], a[mt], b[nt2][0], b[nt2][2]);
                mma16816(acc[mt][nt2 * 2 + 1], a[mt], b[nt2][1], b[nt2][3]);
            }
    }
}

// ============================ GEMM 1: branch GEMM ============================
// C[M,128] = A'[M,512] @ B'[128,512]^T, plain fp16 GEMM (split-2 symmetric).
// grid (tiles, 9). branch 0 -> z2 slice 0 (fp16 pairs); 1..8 -> H fp32*out_norm.
__global__ __launch_bounds__(256, 2)
void mma_gemm1(const __half* __restrict__ A2, const __half* __restrict__ Bbase,
               __half* __restrict__ z2out, float* __restrict__ Hout,
               const float* __restrict__ out_norm)
{
    extern __shared__ __align__(16) char smem[];
    const int tid = threadIdx.x;
    const int wid = tid >> 5, lane = tid & 31;
    const int warpM = wid & 1, warpN = wid >> 1;
    const int branch = blockIdx.y;
    const int rowBase = blockIdx.x * 128;
    const int lda = 2 * IND;            // 512
    const int nC = lda >> 6;            // 8 chunks
    const __half* B2 = Bbase + (size_t)branch * OUTD * lda;
    const uint32_t smemBase = smem_u32(smem);
    float acc[4][4][4] = {};

    auto load_stage = [&](int c, int buf) {
        int k0 = c * 64;
        char* sAb = smem + buf * 2 * ATILE;
        char* sBb = sAb + ATILE;
        #pragma unroll
        for (int i = 0; i < 4; ++i) {
            int idx = tid + i * 256;
            int r = idx >> 3, c16 = idx & 7;
            int grow = rowBase + r; if (grow > NN - 1) grow = NN - 1;
            CP_ASYNC16(smem_u32(sAb + r * SROW + c16 * 16),
                       A2 + (size_t)grow * lda + k0 + c16 * 8);
            CP_ASYNC16(smem_u32(sBb + r * SROW + c16 * 16),
                       B2 + (size_t)r * lda + k0 + c16 * 8);
        }
    };

    load_stage(0, 0); CP_COMMIT();
    load_stage(1, 1); CP_COMMIT();
    for (int c = 0; c < nC; ++c) {
        if (c + 1 < nC) CP_WAIT1(); else CP_WAIT0();
        __syncthreads();
        if (c + 2 < nC) { load_stage(c + 2, (c + 2) % NSTAGE0); CP_COMMIT(); }
        uint32_t sAb = smemBase + (c % NSTAGE0) * 2 * ATILE;
        chunk_mma(sAb, sAb + ATILE, warpM, warpN, lane, acc);
    }

    const int g = lane >> 2, t4 = lane & 3;
    #pragma unroll
    for (int mt = 0; mt < 4; ++mt) {
        int row0 = rowBase + warpM * 64 + mt * 16 + g;
        int row1 = row0 + 8;
        if (branch == 0) {
            #pragma unroll
            for (int nt = 0; nt < 4; ++nt) {
                int col = warpN * 32 + nt * 8 + 2 * t4;
                #pragma unroll
                for (int half = 0; half < 2; ++half) {
                    int row = half ? row1 : row0;
                    if (row >= NN) continue;
                    float c0 = acc[mt][nt][half * 2 + 0];
                    float c1 = acc[mt][nt][half * 2 + 1];
                    __half2 hi = __floats2half2_rn(c0, c1);
                    __half2 lo = __floats2half2_rn(c0 - __half2float(hi.x),
                                                   c1 - __half2float(hi.y));
                    __half* zr = z2out + (size_t)row * NK * 2 * OUTD;
                    *reinterpret_cast<__half2*>(zr + col) = hi;
                    *reinterpret_cast<__half2*>(zr + OUTD + col) = lo;
                }
            }
        } else {
            float* C = Hout + (size_t)(branch - 1) * NN * OUTD;
            float s0 = (row0 < NN) ? out_norm[row0] : 0.f;
            float s1 = (row1 < NN) ? out_norm[row1] : 0.f;
            #pragma unroll
            for (int nt = 0; nt < 4; ++nt) {
                int col = warpN * 32 + nt * 8 + 2 * t4;
                if (row0 < NN) {
                    float2 v = make_float2(acc[mt][nt][0] * s0, acc[mt][nt][1] * s0);
                    *reinterpret_cast<float2*>(C + (size_t)row0 * OUTD + col) = v;
                }
                if (row1 < NN) {
                    float2 v = make_float2(acc[mt][nt][2] * s1, acc[mt][nt][3] * s1);
                    *reinterpret_cast<float2*>(C + (size_t)row1 * OUTD + col) = v;
                }
            }
        }
    }
}

// ============================ GEMM 2: WC/WD, persistent B ===================
// C[M,128] = z2[M,256] @ w2t[128,256]^T * in_norm[row/9]. B (64KB+pad) lives in
// smem for the whole kernel; only A chunks stream (2 buffers, load-after-use).
// grid (2*tiles): branch = blockIdx.x & 1.
#define M2 (NN * NK)
__global__ __launch_bounds__(256, 2)
void mma_gemm2(const __half* __restrict__ A2, const __half* __restrict__ Bbase,
               float* __restrict__ zc, float* __restrict__ zd,
               const float* __restrict__ in_norm)
{
    extern __shared__ __align__(16) char smem[];
    // layout: B chunks [0..3] then A buffers [0..1]
    char* sB = smem;
    char* sA = smem + 4 * ATILE;

    const int tid = threadIdx.x;
    const int wid = tid >> 5, lane = tid & 31;
    const int warpM = wid & 1, warpN = wid >> 1;
    const int branch = blockIdx.x & 1;
    const int rowBase = (blockIdx.x >> 1) * 128;
    const int lda = 2 * OUTD;           // 256
    const __half* B2 = Bbase + (size_t)branch * OUTD * lda;
    float* C = branch ? zd : zc;
    const uint32_t sB_u = smem_u32(sB);
    const uint32_t sA_u = smem_u32(sA);
    float acc[4][4][4] = {};

    auto loadA = [&](int c, int buf) {
        char* dst = sA + buf * ATILE;
        int k0 = c * 64;
        #pragma unroll
        for (int i = 0; i < 4; ++i) {
            int idx = tid + i * 256;
            int r = idx >> 3, c16 = idx & 7;
            int grow = rowBase + r; if (grow > M2 - 1) grow = M2 - 1;
            CP_ASYNC16(smem_u32(dst + r * SROW + c16 * 16),
                       A2 + (size_t)grow * lda + k0 + c16 * 8);
        }
    };

    // persistent B: 4 chunk-tiles (4096 16B segs -> 16 per thread)
    #pragma unroll
    for (int ch = 0; ch < 4; ++ch) {
        char* dst = sB + ch * ATILE;
        #pragma unroll
        for (int i = 0; i < 4; ++i) {
            int idx = tid + i * 256;
            int r = idx >> 3, c16 = idx & 7;
            CP_ASYNC16(smem_u32(dst + r * SROW + c16 * 16),
                       B2 + (size_t)r * lda + ch * 64 + c16 * 8);
        }
    }
    loadA(0, 0); CP_COMMIT();           // G0 = B + A0
    loadA(1, 1); CP_COMMIT();           // G1 = A1

    #pragma unroll
    for (int c = 0; c < 4; ++c) {
        if (c + 1 < 4) CP_WAIT1(); else CP_WAIT0();
        __syncthreads();                // A[c%2] + (c==0: all B) ready
        chunk_mma(sA_u + (c & 1) * ATILE, sB_u + c * ATILE, warpM, warpN, lane, acc);
        if (c + 2 < 4) {
            __syncthreads();            // everyone done with buffer (c%2)
            loadA(c + 2, c & 1); CP_COMMIT();
        }
    }

    const int g = lane >> 2, t4 = lane & 3;
    #pragma unroll
    for (int mt = 0; mt < 4; ++mt) {
        int row0 = rowBase + warpM * 64 + mt * 16 + g;
        int row1 = row0 + 8;
        float s0 = (row0 < M2) ? in_norm[row0 / NK] : 0.f;
        float s1 = (row1 < M2) ? in_norm[row1 / NK] : 0.f;
        #pragma unroll
        for (int nt = 0; nt < 4; ++nt) {
            int col = warpN * 32 + nt * 8 + 2 * t4;
            if (row0 < M2) {
                float2 v = make_float2(acc[mt][nt][0] * s0, acc[mt][nt][1] * s0);
                *reinterpret_cast<float2*>(C + (size_t)row0 * OUTD + col) = v;
            }
            if (row1 < M2) {
                float2 v = make_float2(acc[mt][nt][2] * s1, acc[mt][nt][3] * s1);
                *reinterpret_cast<float2*>(C + (size_t)row1 * OUTD + col) = v;
            }
        }
    }
}

// ---------------- edge-list build: bucket (sector,src) <- dst ----------------
__global__ __launch_bounds__(256)
void build_lists(const int* __restrict__ rows, const int* __restrict__ cols,
                 int* __restrict__ cnt, int* __restrict__ eidx)
{
    int i = blockIdx.x * blockDim.x + threadIdx.x;
    if (i >= NS * NEP) return;
    int s = i / NEP;
    int src = rows[i];
    int dst = cols[i];
    int b = s * NN + src;
    int slot = atomicAdd(&cnt[b], 1);
    if (slot < EMAX) eidx[(size_t)b * EMAX + slot] = dst;
}

// ---------------- gather aggregation: one warp per (sector,src) --------------
__global__ __launch_bounds__(256)
void gather_agg(const int* __restrict__ cnt, const int* __restrict__ eidx,
                const float* __restrict__ H, __half* __restrict__ z2)
{
    int gw   = (blockIdx.x * blockDim.x + threadIdx.x) >> 5;
    int lane = threadIdx.x & 31;
    if (gw >= NS * NN) return;
    int s = gw / NN, src = gw - s * NN;
    int c = cnt[gw]; if (c > EMAX) c = EMAX;
    const int* lst = eidx + (size_t)gw * EMAX;
    const float* Hs = H + (size_t)s * NN * OUTD;

    float4 acc = make_float4(0.f, 0.f, 0.f, 0.f);
    for (int i = 0; i < c; ++i) {
        int dst = lst[i];
        float4 v = *(reinterpret_cast<const float4*>(Hs + (size_t)dst * OUTD) + lane);
        acc.x += v.x; acc.y += v.y; acc.z += v.z; acc.w += v.w;
    }

    __half2 h01 = __floats2half2_rn(acc.x, acc.y);
    __half2 h23 = __floats2half2_rn(acc.z, acc.w);
    __half2 l01 = __floats2half2_rn(acc.x - __half2float(h01.x),
                                    acc.y - __half2float(h01.y));
    __half2 l23 = __floats2half2_rn(acc.z - __half2float(h23.x),
                                    acc.w - __half2float(h23.y));
    __half* zp = z2 + ((size_t)src * NK + 1 + s) * (2 * OUTD);
    *reinterpret_cast<__half2*>(zp + lane * 4 + 0) = h01;
    *reinterpret_cast<__half2*>(zp + lane * 4 + 2) = h23;
    *reinterpret_cast<__half2*>(zp + OUTD + lane * 4 + 0) = l01;
    *reinterpret_cast<__half2*>(zp + OUTD + lane * 4 + 2) = l23;
}

// ---------------- per-node interaction (verified) ----------------------------
__global__ __launch_bounds__(128)
void interact(const float* __restrict__ zc, const float* __restrict__ zd,
              const float* __restrict__ gw, const float* __restrict__ gb,
              float* __restrict__ out)
{
    const int n = blockIdx.x;
    const int t = threadIdx.x;
    __shared__ float sc[NK][OUTD];
    __shared__ float sd[NK][OUTD];
    __shared__ float ac[NK][NK];
    __shared__ float ad[NK][NK];
    __shared__ float red[4];
    __shared__ float s_beta;

    const float* zcn = zc + (size_t)n * NK * OUTD;
    const float* zdn = zd + (size_t)n * NK * OUTD;
    #pragma unroll
    for (int r = 0; r < NK; ++r) {
        sc[r][t] = zcn[r * OUTD + t];
        sd[r][t] = zdn[r * OUTD + t];
    }
    __syncthreads();

    const int warp = t >> 5, lane = t & 31;
    for (int d = warp; d < 162; d += 4) {
        int which = (d >= 81);
        int p = which ? d - 81 : d;
        int k = p / 9, j = p - 9 * k;
        const float* a = which ? sd[k] : sc[k];
        const float* b = which ? sd[j] : sc[j];
        float part = 0.f;
        #pragma unroll
        for (int o = 0; o < 4; ++o) part += a[lane + 32 * o] * b[lane + 32 * o];
        #pragma unroll
        for (int off = 16; off; off >>= 1)
            part += __shfl_down_sync(0xffffffffu, part, off);
        if (lane == 0) { if (which) ad[k][j] = part; else ac[k][j] = part; }
    }
    __syncthreads();

    if (t < 9) {
        float row[NK]; float m = -1e30f;
        #pragma unroll
        for (int j = 0; j < NK; ++j) { row[j] = ac[t][j]; m = fmaxf(m, row[j]); }
        float ssum = 0.f;
        #pragma unroll
        for (int j = 0; j < NK; ++j) { row[j] = expf(row[j] - m); ssum += row[j]; }
        float inv = 1.f / ssum;
        #pragma unroll
        for (int j = 0; j < NK; ++j) ac[t][j] = row[j] * inv;
    } else if (t >= 16 && t < 25) {
        int k = t - 16;
        float q = ad[k][k];
        float row[NK]; float m = -1e30f;
        #pragma unroll
        for (int j = 0; j < NK; ++j) { row[j] = q - ad[k][j]; m = fmaxf(m, row[j]); }
        float ssum = 0.f;
        #pragma unroll
        for (int j = 0; j < NK; ++j) { row[j] = expf(row[j] - m); ssum += row[j]; }
        float inv = 1.f / ssum;
        #pragma unroll
        for (int j = 0; j < NK; ++j) ad[k][j] = row[j] * inv;
    }
    __syncthreads();

    float zcom[NK], zdis[NK];
    #pragma unroll
    for (int k = 0; k < NK; ++k) {
        float a0 = 0.f, a1 = 0.f;
        #pragma unroll
        for (int j = 0; j < NK; ++j) {
            a0 += ac[k][j] * sc[j][t];
            a1 += ad[k][j] * sd[j][t];
        }
        zcom[k] = a0;
        zdis[k] = sd[k][t] - a1;
    }

    float gp = 0.f;
    #pragma unroll
    for (int k = 0; k < NK; ++k)
        gp += zcom[k] * gw[k * OUTD + t] + zdis[k] * gw[NK * OUTD + k * OUTD + t];
    #pragma unroll
    for (int off = 16; off; off >>= 1)
        gp += __shfl_down_sync(0xffffffffu, gp, off);
    if (lane == 0) red[warp] = gp;
    __syncthreads();
    if (t == 0) {
        float tot = red[0] + red[1] + red[2] + red[3] + gb[0];
        s_beta = 1.f / (1.f + expf(-tot));
    }
    __syncthreads();
    const float beta = s_beta;

    float* op = out + (size_t)n * (NK * OUTD);
    #pragma unroll
    for (int k = 0; k < NK; ++k)
        op[k * OUTD + t] = beta * zcom[k] + (1.f - beta) * zdis[k];
}

// ---------------- launch ------------------------------------------------------
extern "C" void kernel_launch(void* const* d_in, const int* in_sizes, int n_in,
                              void* d_out, int out_size)
{
    const float* x        = (const float*)d_in[0];
    const float* W_self   = (const float*)d_in[1];
    const float* W_sect   = (const float*)d_in[2];
    const float* WC       = (const float*)d_in[3];
    const float* WD       = (const float*)d_in[4];
    const float* gate_w   = (const float*)d_in[5];
    const float* gate_b   = (const float*)d_in[6];
    const float* out_norm = (const float*)d_in[7];
    const float* in_norm  = (const float*)d_in[8];
    const int*   rows     = (const int*)d_in[9];
    const int*   cols     = (const int*)d_in[10];
    float* out = (float*)d_out;

    float *H, *zc, *zd;
    __half *x2, *z2, *w1t, *w2t;
    int *cnt, *eidx;
    cudaGetSymbolAddress((void**)&H,    d_H);
    cudaGetSymbolAddress((void**)&zc,   d_zc);
    cudaGetSymbolAddress((void**)&zd,   d_zd);
    cudaGetSymbolAddress((void**)&x2,   d_x2);
    cudaGetSymbolAddress((void**)&z2,   d_z2);
    cudaGetSymbolAddress((void**)&w1t,  d_w1t);
    cudaGetSymbolAddress((void**)&w2t,  d_w2t);
    cudaGetSymbolAddress((void**)&cnt,  d_cnt);
    cudaGetSymbolAddress((void**)&eidx, d_eidx);

    cudaFuncSetAttribute(mma_gemm1, cudaFuncAttributeMaxDynamicSharedMemorySize, SMEM_TOT);
    cudaFuncSetAttribute(mma_gemm2, cudaFuncAttributeMaxDynamicSharedMemorySize, SMEM_TOT);

    // (0) convert x -> fp16 [hi|lo]; also zeroes the bucket counters
    conv_x<<<(NN * IND + 255) / 256, 256>>>(x, x2, cnt);

    // (1) build per-(sector,src) edge lists
    build_lists<<<(NS * NEP + 255) / 256, 256>>>(rows, cols, cnt, eidx);

    // (2) all weight conversions in one launch (9 x w1t, 2 x w2t)
    conv_w_all<<<dim3((IND * OUTD + 255) / 256, 11), 256>>>(W_self, W_sect, WC, WD, w1t, w2t);

    // (3) branch GEMMs, fp16 split-2 (Kd=512); branch 0 writes z2 directly
    mma_gemm1<<<dim3((NN + 127) / 128, NK), 256, SMEM_TOT>>>(
        x2, w1t, z2, H, out_norm);

    // (4) gather aggregation -> z2 slices 1..8 (fp16 pairs)
    gather_agg<<<(NS * NN * 32 + 255) / 256, 256>>>(cnt, eidx, H, z2);

    // (5) WC/WD GEMMs, persistent-B in smem (Kd=256), branch interleaved
    mma_gemm2<<<dim3(2 * ((M2 + 127) / 128), 1), 256, SMEM_TOT>>>(
        z2, w2t, zc, zd, in_norm);

    // (6) per-node interaction + gate
    interact<<<NN, 128>>>(zc, zd, gate_w, gate_b, out);
}